// round 1
// baseline (speedup 1.0000x reference)
#include <cuda_runtime.h>

#define N_NODES 100000
#define N_EDGES 1600000
#define HID 64
#define LAYERS 3

typedef unsigned long long ull;

// ---------- device scratch (no allocation allowed) ----------
__device__ float g_h[N_NODES * HID];
__device__ float g_agg[N_NODES * HID];
__device__ float g_xA[N_NODES * 3];
__device__ float g_xB[N_NODES * 3];
__device__ float g_tmean[HID];

// ---------- packed f32x2 helpers ----------
__device__ __forceinline__ ull ffma2(ull a, ull b, ull c) {
    ull d;
    asm("fma.rn.f32x2 %0, %1, %2, %3;" : "=l"(d) : "l"(a), "l"(b), "l"(c));
    return d;
}
__device__ __forceinline__ ull pack2(float x, float y) {
    ull r; asm("mov.b64 %0, {%1, %2};" : "=l"(r) : "f"(x), "f"(y)); return r;
}
__device__ __forceinline__ float2 unpack2(ull v) {
    float2 r; asm("mov.b64 {%0, %1}, %2;" : "=f"(r.x), "=f"(r.y) : "l"(v)); return r;
}
__device__ __forceinline__ float silu(float v) {
    return __fdividef(v, 1.0f + __expf(-v));
}

// ---------- time embedding: tmean[j] = mean_b(silu(t*w1+b1)) @ w2 + b2 ----------
__global__ void temb_kernel(const float* __restrict__ t,
                            const float* __restrict__ w1, const float* __restrict__ b1,
                            const float* __restrict__ w2, const float* __restrict__ b2,
                            int B) {
    __shared__ float sm[HID];
    int j = threadIdx.x;
    float w = w1[j], bb = b1[j];
    float acc = 0.f;
    for (int b = 0; b < B; b++) acc += silu(t[b] * w + bb);
    sm[j] = acc / (float)B;
    __syncthreads();
    float o = b2[j];
    for (int k = 0; k < HID; k++) o += sm[k] * w2[k * HID + j];
    g_tmean[j] = o;
}

// ---------- h init: h[i,j] = emb[z[i],j] + tmean[j] ----------
__global__ void init_h_kernel(const int* __restrict__ z, const float* __restrict__ emb) {
    int i = blockIdx.x * blockDim.x + threadIdx.x;
    if (i >= N_NODES * HID) return;
    int node = i >> 6, j = i & 63;
    g_h[i] = emb[z[node] * HID + j] + g_tmean[j];
}

// ---------- shared memory layouts ----------
// edge kernel: w1(129x64 interleaved) + w2(64x64) + cw1(64x64) + cw2(64) + 4 biases + sef
#define E_SW1    0
#define E_SW2    (129 * 64)
#define E_SC1    (E_SW2 + 64 * 64)
#define E_SC2    (E_SC1 + 64 * 64)
#define E_EB1    (E_SC2 + 64)
#define E_EB2    (E_EB1 + 64)
#define E_CB1    (E_EB2 + 64)
#define E_CB2    (E_CB1 + 64)
#define E_SEF    (E_CB2 + 4)
#define E_FLOATS (E_SEF + 8 * 136)
#define ESMEM_BYTES (E_FLOATS * 4)

#define N_SW1    0
#define N_SW2    (128 * 64)
#define N_B1     (N_SW2 + 64 * 64)
#define N_B2     (N_B1 + 64)
#define N_SEF    (N_B2 + 64)
#define N_FLOATS (N_SEF + 8 * 136)
#define NSMEM_BYTES (N_FLOATS * 4)

// ---------- edge kernel: warp per edge ----------
__global__ void __launch_bounds__(256)
edge_kernel(const float* __restrict__ x, float* __restrict__ xn,
            const int* __restrict__ ei,
            const float* __restrict__ ew1, const float* __restrict__ eb1g,
            const float* __restrict__ ew2, const float* __restrict__ eb2g,
            const float* __restrict__ cw1, const float* __restrict__ cb1g,
            const float* __restrict__ cw2, const float* __restrict__ cb2g,
            int do_agg) {
    extern __shared__ float sm[];
    int tid = threadIdx.x;
    // stage weights, interleaved pairs: dest[k*64 + 2*j + h] = w[k*64 + j + h*32]
    for (int i = tid; i < 129 * 64; i += 256) {
        int k = i >> 6, c = i & 63;
        sm[E_SW1 + i] = ew1[k * 64 + (c >> 1) + ((c & 1) << 5)];
    }
    for (int i = tid; i < 64 * 64; i += 256) {
        int k = i >> 6, c = i & 63;
        int srcidx = k * 64 + (c >> 1) + ((c & 1) << 5);
        sm[E_SW2 + i] = ew2[srcidx];
        sm[E_SC1 + i] = cw1[srcidx];
    }
    if (tid < 64) {
        sm[E_SC2 + tid] = cw2[tid];
        sm[E_EB1 + tid] = eb1g[tid];
        sm[E_EB2 + tid] = eb2g[tid];
        sm[E_CB1 + tid] = cb1g[tid];
    }
    if (tid == 0) sm[E_CB2] = cb2g[0];
    __syncthreads();

    const int lane = tid & 31;
    const int wid = (blockIdx.x * 256 + tid) >> 5;
    const int nw = (gridDim.x * 256) >> 5;
    float* sef = sm + E_SEF + (tid >> 5) * 136;
    const ull* W1 = (const ull*)(sm + E_SW1);
    const ull* W2 = (const ull*)(sm + E_SW2);
    const ull* C1 = (const ull*)(sm + E_SC1);
    const float cb2s = sm[E_CB2];
    const ull bias1 = pack2(sm[E_EB1 + lane], sm[E_EB1 + lane + 32]);
    const ull bias2 = pack2(sm[E_EB2 + lane], sm[E_EB2 + lane + 32]);
    const ull biasc = pack2(sm[E_CB1 + lane], sm[E_CB1 + lane + 32]);
    const float sc2a = sm[E_SC2 + lane], sc2b = sm[E_SC2 + lane + 32];

    for (int e = wid; e < N_EDGES; e += nw) {
        const int s = ei[e];
        const int d = ei[N_EDGES + e];
        const float dx0 = x[d * 3 + 0] - x[s * 3 + 0];
        const float dx1 = x[d * 3 + 1] - x[s * 3 + 1];
        const float dx2 = x[d * 3 + 2] - x[s * 3 + 2];
        const float r2 = dx0 * dx0 + dx1 * dx1 + dx2 * dx2;
        const float hd0 = g_h[d * 64 + lane], hd1 = g_h[d * 64 + 32 + lane];
        const float hs0 = g_h[s * 64 + lane], hs1 = g_h[s * 64 + 32 + lane];
        sef[lane] = hd0; sef[32 + lane] = hd1;
        sef[64 + lane] = hs0; sef[96 + lane] = hs1;
        __syncwarp();
        // ---- edge MLP layer 1: 129 -> 64 ----
        ull acc = bias1;
        #pragma unroll 8
        for (int k = 0; k < 128; k += 4) {
            float4 v = *(const float4*)&sef[k];
            acc = ffma2(pack2(v.x, v.x), W1[(k + 0) * 32 + lane], acc);
            acc = ffma2(pack2(v.y, v.y), W1[(k + 1) * 32 + lane], acc);
            acc = ffma2(pack2(v.z, v.z), W1[(k + 2) * 32 + lane], acc);
            acc = ffma2(pack2(v.w, v.w), W1[(k + 3) * 32 + lane], acc);
        }
        acc = ffma2(pack2(r2, r2), W1[128 * 32 + lane], acc);
        float2 a1 = unpack2(acc);
        __syncwarp();
        sef[lane] = silu(a1.x); sef[32 + lane] = silu(a1.y);
        __syncwarp();
        // ---- edge MLP layer 2: 64 -> 64, silu -> m ----
        ull acc2 = bias2;
        #pragma unroll 8
        for (int k = 0; k < 64; k += 4) {
            float4 v = *(const float4*)&sef[k];
            acc2 = ffma2(pack2(v.x, v.x), W2[(k + 0) * 32 + lane], acc2);
            acc2 = ffma2(pack2(v.y, v.y), W2[(k + 1) * 32 + lane], acc2);
            acc2 = ffma2(pack2(v.z, v.z), W2[(k + 2) * 32 + lane], acc2);
            acc2 = ffma2(pack2(v.w, v.w), W2[(k + 3) * 32 + lane], acc2);
        }
        float2 a2 = unpack2(acc2);
        const float m0 = silu(a2.x), m1 = silu(a2.y);
        __syncwarp();
        sef[lane] = m0; sef[32 + lane] = m1;
        __syncwarp();
        // ---- coord MLP hidden: 64 -> 64, silu ----
        ull acc3 = biasc;
        #pragma unroll 8
        for (int k = 0; k < 64; k += 4) {
            float4 v = *(const float4*)&sef[k];
            acc3 = ffma2(pack2(v.x, v.x), C1[(k + 0) * 32 + lane], acc3);
            acc3 = ffma2(pack2(v.y, v.y), C1[(k + 1) * 32 + lane], acc3);
            acc3 = ffma2(pack2(v.z, v.z), C1[(k + 2) * 32 + lane], acc3);
            acc3 = ffma2(pack2(v.w, v.w), C1[(k + 3) * 32 + lane], acc3);
        }
        float2 a3 = unpack2(acc3);
        // ---- coord MLP out: dot(ch, cw2) + cb2 ----
        float p = silu(a3.x) * sc2a + silu(a3.y) * sc2b;
        #pragma unroll
        for (int o = 16; o; o >>= 1) p += __shfl_xor_sync(0xffffffffu, p, o);
        const float cwv = p + cb2s;
        if (lane < 3) {
            const float dv = (lane == 0) ? dx0 : ((lane == 1) ? dx1 : dx2);
            atomicAdd(&xn[d * 3 + lane], dv * cwv);
        }
        if (do_agg) {
            atomicAdd(&g_agg[d * 64 + lane], m0);
            atomicAdd(&g_agg[d * 64 + 32 + lane], m1);
        }
    }
}

// ---------- node kernel: warp per node, h += MLP([h, agg]) ----------
__global__ void __launch_bounds__(256)
node_kernel(const float* __restrict__ nw1, const float* __restrict__ nb1g,
            const float* __restrict__ nw2, const float* __restrict__ nb2g) {
    extern __shared__ float sm[];
    int tid = threadIdx.x;
    for (int i = tid; i < 128 * 64; i += 256) {
        int k = i >> 6, c = i & 63;
        sm[N_SW1 + i] = nw1[k * 64 + (c >> 1) + ((c & 1) << 5)];
    }
    for (int i = tid; i < 64 * 64; i += 256) {
        int k = i >> 6, c = i & 63;
        sm[N_SW2 + i] = nw2[k * 64 + (c >> 1) + ((c & 1) << 5)];
    }
    if (tid < 64) { sm[N_B1 + tid] = nb1g[tid]; sm[N_B2 + tid] = nb2g[tid]; }
    __syncthreads();

    const int lane = tid & 31;
    const int wid = (blockIdx.x * 256 + tid) >> 5;
    const int nw = (gridDim.x * 256) >> 5;
    float* sef = sm + N_SEF + (tid >> 5) * 136;
    const ull* W1 = (const ull*)(sm + N_SW1);
    const ull* W2 = (const ull*)(sm + N_SW2);
    const ull b1p = pack2(sm[N_B1 + lane], sm[N_B1 + lane + 32]);
    const ull b2p = pack2(sm[N_B2 + lane], sm[N_B2 + lane + 32]);

    for (int n = wid; n < N_NODES; n += nw) {
        const float h0 = g_h[n * 64 + lane], h1 = g_h[n * 64 + 32 + lane];
        const float a0 = g_agg[n * 64 + lane], a1 = g_agg[n * 64 + 32 + lane];
        sef[lane] = h0; sef[32 + lane] = h1;
        sef[64 + lane] = a0; sef[96 + lane] = a1;
        __syncwarp();
        ull acc = b1p;
        #pragma unroll 8
        for (int k = 0; k < 128; k += 4) {
            float4 v = *(const float4*)&sef[k];
            acc = ffma2(pack2(v.x, v.x), W1[(k + 0) * 32 + lane], acc);
            acc = ffma2(pack2(v.y, v.y), W1[(k + 1) * 32 + lane], acc);
            acc = ffma2(pack2(v.z, v.z), W1[(k + 2) * 32 + lane], acc);
            acc = ffma2(pack2(v.w, v.w), W1[(k + 3) * 32 + lane], acc);
        }
        float2 u = unpack2(acc);
        __syncwarp();
        sef[lane] = silu(u.x); sef[32 + lane] = silu(u.y);
        __syncwarp();
        ull acc2 = b2p;
        #pragma unroll 8
        for (int k = 0; k < 64; k += 4) {
            float4 v = *(const float4*)&sef[k];
            acc2 = ffma2(pack2(v.x, v.x), W2[(k + 0) * 32 + lane], acc2);
            acc2 = ffma2(pack2(v.y, v.y), W2[(k + 1) * 32 + lane], acc2);
            acc2 = ffma2(pack2(v.z, v.z), W2[(k + 2) * 32 + lane], acc2);
            acc2 = ffma2(pack2(v.w, v.w), W2[(k + 3) * 32 + lane], acc2);
        }
        float2 o = unpack2(acc2);
        g_h[n * 64 + lane] = h0 + o.x;
        g_h[n * 64 + 32 + lane] = h1 + o.y;
    }
}

// ---------- launch ----------
extern "C" void kernel_launch(void* const* d_in, const int* in_sizes, int n_in,
                              void* d_out, int out_size) {
    const float* x   = (const float*)d_in[0];
    const int*   z   = (const int*)d_in[1];
    const float* t   = (const float*)d_in[2];
    const int*   ei  = (const int*)d_in[3];
    const float* emb = (const float*)d_in[4];
    const float* tw1 = (const float*)d_in[5];
    const float* tb1 = (const float*)d_in[6];
    const float* tw2 = (const float*)d_in[7];
    const float* tb2 = (const float*)d_in[8];
    const float* ew1 = (const float*)d_in[9];
    const float* eb1 = (const float*)d_in[10];
    const float* ew2 = (const float*)d_in[11];
    const float* eb2 = (const float*)d_in[12];
    const float* cw1 = (const float*)d_in[13];
    const float* cb1 = (const float*)d_in[14];
    const float* cw2 = (const float*)d_in[15];
    const float* cb2 = (const float*)d_in[16];
    const float* nw1 = (const float*)d_in[17];
    const float* nb1 = (const float*)d_in[18];
    const float* nw2 = (const float*)d_in[19];
    const float* nb2 = (const float*)d_in[20];
    float* out = (float*)d_out;
    const int B = in_sizes[2];

    float *pxA, *pxB, *pagg;
    cudaGetSymbolAddress((void**)&pxA, g_xA);
    cudaGetSymbolAddress((void**)&pxB, g_xB);
    cudaGetSymbolAddress((void**)&pagg, g_agg);

    cudaFuncSetAttribute(edge_kernel, cudaFuncAttributeMaxDynamicSharedMemorySize, ESMEM_BYTES);
    cudaFuncSetAttribute(node_kernel, cudaFuncAttributeMaxDynamicSharedMemorySize, NSMEM_BYTES);

    const int EBLK = 444;   // 3 blocks/SM (71 KB smem each)
    const int NBLK = 592;   // 4 blocks/SM

    temb_kernel<<<1, 64>>>(t, tw1, tb1, tw2, tb2, B);
    init_h_kernel<<<(N_NODES * HID + 255) / 256, 256>>>(z, emb);
    cudaMemcpyAsync(pxA, x, (size_t)N_NODES * 3 * sizeof(float), cudaMemcpyDeviceToDevice, 0);

    // ---- layer 0: x in xA, x' in xB ----
    cudaMemsetAsync(pagg, 0, (size_t)N_NODES * HID * sizeof(float), 0);
    cudaMemcpyAsync(pxB, pxA, (size_t)N_NODES * 3 * sizeof(float), cudaMemcpyDeviceToDevice, 0);
    edge_kernel<<<EBLK, 256, ESMEM_BYTES>>>(pxA, pxB, ei,
        ew1 + 0 * 129 * 64, eb1 + 0 * 64, ew2 + 0 * 4096, eb2 + 0 * 64,
        cw1 + 0 * 4096, cb1 + 0 * 64, cw2 + 0 * 64, cb2 + 0, 1);
    node_kernel<<<NBLK, 256, NSMEM_BYTES>>>(nw1 + 0 * 128 * 64, nb1 + 0 * 64,
                                            nw2 + 0 * 4096, nb2 + 0 * 64);

    // ---- layer 1: x in xB, x' in xA ----
    cudaMemsetAsync(pagg, 0, (size_t)N_NODES * HID * sizeof(float), 0);
    cudaMemcpyAsync(pxA, pxB, (size_t)N_NODES * 3 * sizeof(float), cudaMemcpyDeviceToDevice, 0);
    edge_kernel<<<EBLK, 256, ESMEM_BYTES>>>(pxB, pxA, ei,
        ew1 + 1 * 129 * 64, eb1 + 1 * 64, ew2 + 1 * 4096, eb2 + 1 * 64,
        cw1 + 1 * 4096, cb1 + 1 * 64, cw2 + 1 * 64, cb2 + 1, 1);
    node_kernel<<<NBLK, 256, NSMEM_BYTES>>>(nw1 + 1 * 128 * 64, nb1 + 1 * 64,
                                            nw2 + 1 * 4096, nb2 + 1 * 64);

    // ---- layer 2: x in xA, x' directly into d_out; node MLP + agg are dead ----
    cudaMemcpyAsync(out, pxA, (size_t)N_NODES * 3 * sizeof(float), cudaMemcpyDeviceToDevice, 0);
    edge_kernel<<<EBLK, 256, ESMEM_BYTES>>>(pxA, out, ei,
        ew1 + 2 * 129 * 64, eb1 + 2 * 64, ew2 + 2 * 4096, eb2 + 2 * 64,
        cw1 + 2 * 4096, cb1 + 2 * 64, cw2 + 2 * 64, cb2 + 2, 0);
}

// round 2
// speedup vs baseline: 1.6777x; 1.6777x over previous
#include <cuda_runtime.h>

#define N_NODES 100000
#define N_EDGES 1600000
#define HID 64

typedef unsigned long long ull;

// ---------- device scratch ----------
__device__ float g_h[N_NODES * HID];
__device__ float g_agg[N_NODES * HID];
__device__ float g_xA[N_NODES * 3];
__device__ float g_xB[N_NODES * 3];
__device__ float g_tmean[HID];

// ---------- packed f32x2 helpers ----------
__device__ __forceinline__ ull ffma2(ull a, ull b, ull c) {
    ull d;
    asm("fma.rn.f32x2 %0, %1, %2, %3;" : "=l"(d) : "l"(a), "l"(b), "l"(c));
    return d;
}
__device__ __forceinline__ ull pack2(float x, float y) {
    ull r; asm("mov.b64 %0, {%1, %2};" : "=l"(r) : "f"(x), "f"(y)); return r;
}
__device__ __forceinline__ float2 unpack2(ull v) {
    float2 r; asm("mov.b64 {%0, %1}, %2;" : "=f"(r.x), "=f"(r.y) : "l"(v)); return r;
}
__device__ __forceinline__ float silu(float v) {
    return __fdividef(v, 1.0f + __expf(-v));
}

// ---------- time embedding ----------
__global__ void temb_kernel(const float* __restrict__ t,
                            const float* __restrict__ w1, const float* __restrict__ b1,
                            const float* __restrict__ w2, const float* __restrict__ b2,
                            int B) {
    __shared__ float sm[HID];
    int j = threadIdx.x;
    float w = w1[j], bb = b1[j];
    float acc = 0.f;
    for (int b = 0; b < B; b++) acc += silu(t[b] * w + bb);
    sm[j] = acc / (float)B;
    __syncthreads();
    float o = b2[j];
    for (int k = 0; k < HID; k++) o += sm[k] * w2[k * HID + j];
    g_tmean[j] = o;
}

// ---------- h init ----------
__global__ void init_h_kernel(const int* __restrict__ z, const float* __restrict__ emb) {
    int i = blockIdx.x * blockDim.x + threadIdx.x;
    if (i >= N_NODES * HID) return;
    int node = i >> 6, j = i & 63;
    g_h[i] = emb[z[node] * HID + j] + g_tmean[j];
}

// ---------- edge kernel smem layout (floats) ----------
// Weight quads: quad q of row k = {w[k][2q], w[k][2q+32], w[k][2q+1], w[k][2q+33]}
// -> read as ulonglong2: .x = pair for acc[2q], .y = pair for acc[2q+1]
#define SM_W1    0
#define SM_W2    (SM_W1 + 129 * 64)
#define SM_C1    (SM_W2 + 64 * 64)
#define SM_CW2   (SM_C1 + 64 * 64)
#define SM_B1    (SM_CW2 + 64)
#define SM_B2    (SM_B1 + 64)
#define SM_CB1   (SM_B2 + 64)
#define SM_CB2   (SM_CB1 + 64)
#define SM_NIDX  (SM_CB2 + 4)
#define SM_FBUF  (SM_NIDX + 16 * 64)
#define SM_TOTAL (SM_FBUF + 16 * 32 * 65)
#define ESMEM_BYTES (SM_TOTAL * 4)

#define NGROUPS (N_EDGES / 32)

// ---------- edge kernel: warp = 32 edges, lane = edge, outputs in packed regs ----------
__global__ void __launch_bounds__(512, 1)
edge_kernel(const float* __restrict__ x, float* __restrict__ xn,
            const int* __restrict__ ei,
            const float* __restrict__ ew1, const float* __restrict__ eb1g,
            const float* __restrict__ ew2, const float* __restrict__ eb2g,
            const float* __restrict__ cw1, const float* __restrict__ cb1g,
            const float* __restrict__ cw2, const float* __restrict__ cb2g,
            int do_agg) {
    extern __shared__ float sm[];
    const int tid = threadIdx.x;

    // ---- stage weights in quad-pair layout ----
    for (int i = tid; i < 129 * 64; i += 512) {
        int k = i >> 6, c = i & 63;
        int q = c >> 2, r = c & 3;
        int j = 2 * q + (r >> 1) + ((r & 1) << 5);
        sm[SM_W1 + i] = ew1[k * 64 + j];
    }
    for (int i = tid; i < 64 * 64; i += 512) {
        int k = i >> 6, c = i & 63;
        int q = c >> 2, r = c & 3;
        int j = 2 * q + (r >> 1) + ((r & 1) << 5);
        sm[SM_W2 + i] = ew2[k * 64 + j];
        sm[SM_C1 + i] = cw1[k * 64 + j];
    }
    if (tid < 32) {
        sm[SM_CW2 + 2 * tid]     = cw2[tid];
        sm[SM_CW2 + 2 * tid + 1] = cw2[tid + 32];
        sm[SM_B1 + 2 * tid]      = eb1g[tid];
        sm[SM_B1 + 2 * tid + 1]  = eb1g[tid + 32];
        sm[SM_B2 + 2 * tid]      = eb2g[tid];
        sm[SM_B2 + 2 * tid + 1]  = eb2g[tid + 32];
        sm[SM_CB1 + 2 * tid]     = cb1g[tid];
        sm[SM_CB1 + 2 * tid + 1] = cb1g[tid + 32];
    }
    if (tid == 0) sm[SM_CB2] = cb2g[0];
    __syncthreads();

    const int lane = tid & 31;
    const int wrp = tid >> 5;
    float* fbuf = sm + SM_FBUF + wrp * (32 * 65);
    int* nidx = (int*)(sm + SM_NIDX) + wrp * 64;
    const ulonglong2* W1v = (const ulonglong2*)(sm + SM_W1);
    const ulonglong2* W2v = (const ulonglong2*)(sm + SM_W2);
    const ulonglong2* C1v = (const ulonglong2*)(sm + SM_C1);
    const ull* CW2v = (const ull*)(sm + SM_CW2);
    const ull* B1v  = (const ull*)(sm + SM_B1);
    const ull* B2v  = (const ull*)(sm + SM_B2);
    const ull* CB1v = (const ull*)(sm + SM_CB1);
    const float cb2s = sm[SM_CB2];

    const int gwarp = (blockIdx.x * 512 + tid) >> 5;
    const int nwarps = (gridDim.x * 512) >> 5;

    for (int g = gwarp; g < NGROUPS; g += nwarps) {
        const int e = g * 32 + lane;
        const int s = ei[e];
        const int d = ei[N_EDGES + e];
        const float dx0 = __ldg(&x[d * 3 + 0]) - __ldg(&x[s * 3 + 0]);
        const float dx1 = __ldg(&x[d * 3 + 1]) - __ldg(&x[s * 3 + 1]);
        const float dx2 = __ldg(&x[d * 3 + 2]) - __ldg(&x[s * 3 + 2]);
        const float r2 = dx0 * dx0 + dx1 * dx1 + dx2 * dx2;
        nidx[lane] = d;
        nidx[32 + lane] = s;

        ull acc[32];
        #pragma unroll
        for (int i = 0; i < 32; i++) acc[i] = B1v[i];

        // ---- phase 1: ef = [h[d], h[s], r2] @ W1, 4 chunks of 32 k ----
        for (int c = 0; c < 4; c++) {
            __syncwarp();
            const int* np = nidx + ((c >> 1) << 5);
            const int coloff = (c & 1) << 5;
            // gather: lane = column, row e2; coalesced LDG, conflict-free STS
            #pragma unroll 8
            for (int e2 = 0; e2 < 32; e2++) {
                int node = np[e2];
                fbuf[e2 * 65 + lane] = __ldg(&g_h[node * 64 + coloff + lane]);
            }
            __syncwarp();
            const ulonglong2* Wk = W1v + c * 32 * 16;
            for (int k = 0; k < 32; k++) {
                float f = fbuf[lane * 65 + k];
                ull fd = pack2(f, f);
                #pragma unroll
                for (int q = 0; q < 16; q++) {
                    ulonglong2 wv = Wk[k * 16 + q];
                    acc[2 * q]     = ffma2(fd, wv.x, acc[2 * q]);
                    acc[2 * q + 1] = ffma2(fd, wv.y, acc[2 * q + 1]);
                }
            }
        }
        { // r2 term (row 128)
            ull fd = pack2(r2, r2);
            #pragma unroll
            for (int q = 0; q < 16; q++) {
                ulonglong2 wv = W1v[128 * 16 + q];
                acc[2 * q]     = ffma2(fd, wv.x, acc[2 * q]);
                acc[2 * q + 1] = ffma2(fd, wv.y, acc[2 * q + 1]);
            }
        }

        // ---- silu -> own row of fbuf (no cross-lane traffic) ----
        #pragma unroll
        for (int i = 0; i < 32; i++) {
            float2 a = unpack2(acc[i]);
            fbuf[lane * 65 + i]      = silu(a.x);
            fbuf[lane * 65 + i + 32] = silu(a.y);
        }

        // ---- phase 2: @ W2 ----
        #pragma unroll
        for (int i = 0; i < 32; i++) acc[i] = B2v[i];
        for (int k = 0; k < 64; k++) {
            float f = fbuf[lane * 65 + k];
            ull fd = pack2(f, f);
            #pragma unroll
            for (int q = 0; q < 16; q++) {
                ulonglong2 wv = W2v[k * 16 + q];
                acc[2 * q]     = ffma2(fd, wv.x, acc[2 * q]);
                acc[2 * q + 1] = ffma2(fd, wv.y, acc[2 * q + 1]);
            }
        }

        // ---- m = silu, store + agg scatter (per-lane rows of g_agg) ----
        if (do_agg) {
            #pragma unroll
            for (int i = 0; i < 32; i++) {
                float2 a = unpack2(acc[i]);
                float m0 = silu(a.x), m1 = silu(a.y);
                fbuf[lane * 65 + i]      = m0;
                fbuf[lane * 65 + i + 32] = m1;
                atomicAdd(&g_agg[d * 64 + i], m0);
                atomicAdd(&g_agg[d * 64 + i + 32], m1);
            }
        } else {
            #pragma unroll
            for (int i = 0; i < 32; i++) {
                float2 a = unpack2(acc[i]);
                fbuf[lane * 65 + i]      = silu(a.x);
                fbuf[lane * 65 + i + 32] = silu(a.y);
            }
        }

        // ---- phase 3: coord MLP hidden ----
        #pragma unroll
        for (int i = 0; i < 32; i++) acc[i] = CB1v[i];
        for (int k = 0; k < 64; k++) {
            float f = fbuf[lane * 65 + k];
            ull fd = pack2(f, f);
            #pragma unroll
            for (int q = 0; q < 16; q++) {
                ulonglong2 wv = C1v[k * 16 + q];
                acc[2 * q]     = ffma2(fd, wv.x, acc[2 * q]);
                acc[2 * q + 1] = ffma2(fd, wv.y, acc[2 * q + 1]);
            }
        }

        // ---- coord output: per-lane dot, then 3 atomics ----
        float p = cb2s;
        #pragma unroll
        for (int i = 0; i < 32; i++) {
            float2 a = unpack2(acc[i]);
            float2 wv = unpack2(CW2v[i]);
            p = fmaf(silu(a.x), wv.x, p);
            p = fmaf(silu(a.y), wv.y, p);
        }
        atomicAdd(&xn[d * 3 + 0], dx0 * p);
        atomicAdd(&xn[d * 3 + 1], dx1 * p);
        atomicAdd(&xn[d * 3 + 2], dx2 * p);
    }
}

// ---------- node kernel (unchanged from round 1) ----------
#define N_SW1    0
#define N_SW2    (128 * 64)
#define N_B1     (N_SW2 + 64 * 64)
#define N_B2     (N_B1 + 64)
#define N_SEF    (N_B2 + 64)
#define N_FLOATS (N_SEF + 8 * 136)
#define NSMEM_BYTES (N_FLOATS * 4)

__global__ void __launch_bounds__(256)
node_kernel(const float* __restrict__ nw1, const float* __restrict__ nb1g,
            const float* __restrict__ nw2, const float* __restrict__ nb2g) {
    extern __shared__ float sm[];
    int tid = threadIdx.x;
    for (int i = tid; i < 128 * 64; i += 256) {
        int k = i >> 6, c = i & 63;
        sm[N_SW1 + i] = nw1[k * 64 + (c >> 1) + ((c & 1) << 5)];
    }
    for (int i = tid; i < 64 * 64; i += 256) {
        int k = i >> 6, c = i & 63;
        sm[N_SW2 + i] = nw2[k * 64 + (c >> 1) + ((c & 1) << 5)];
    }
    if (tid < 64) { sm[N_B1 + tid] = nb1g[tid]; sm[N_B2 + tid] = nb2g[tid]; }
    __syncthreads();

    const int lane = tid & 31;
    const int wid = (blockIdx.x * 256 + tid) >> 5;
    const int nw = (gridDim.x * 256) >> 5;
    float* sef = sm + N_SEF + (tid >> 5) * 136;
    const ull* W1 = (const ull*)(sm + N_SW1);
    const ull* W2 = (const ull*)(sm + N_SW2);
    const ull b1p = pack2(sm[N_B1 + lane], sm[N_B1 + lane + 32]);
    const ull b2p = pack2(sm[N_B2 + lane], sm[N_B2 + lane + 32]);

    for (int n = wid; n < N_NODES; n += nw) {
        const float h0 = g_h[n * 64 + lane], h1 = g_h[n * 64 + 32 + lane];
        const float a0 = g_agg[n * 64 + lane], a1 = g_agg[n * 64 + 32 + lane];
        sef[lane] = h0; sef[32 + lane] = h1;
        sef[64 + lane] = a0; sef[96 + lane] = a1;
        __syncwarp();
        ull acc = b1p;
        #pragma unroll 8
        for (int k = 0; k < 128; k += 4) {
            float4 v = *(const float4*)&sef[k];
            acc = ffma2(pack2(v.x, v.x), W1[(k + 0) * 32 + lane], acc);
            acc = ffma2(pack2(v.y, v.y), W1[(k + 1) * 32 + lane], acc);
            acc = ffma2(pack2(v.z, v.z), W1[(k + 2) * 32 + lane], acc);
            acc = ffma2(pack2(v.w, v.w), W1[(k + 3) * 32 + lane], acc);
        }
        float2 u = unpack2(acc);
        __syncwarp();
        sef[lane] = silu(u.x); sef[32 + lane] = silu(u.y);
        __syncwarp();
        ull acc2 = b2p;
        #pragma unroll 8
        for (int k = 0; k < 64; k += 4) {
            float4 v = *(const float4*)&sef[k];
            acc2 = ffma2(pack2(v.x, v.x), W2[(k + 0) * 32 + lane], acc2);
            acc2 = ffma2(pack2(v.y, v.y), W2[(k + 1) * 32 + lane], acc2);
            acc2 = ffma2(pack2(v.z, v.z), W2[(k + 2) * 32 + lane], acc2);
            acc2 = ffma2(pack2(v.w, v.w), W2[(k + 3) * 32 + lane], acc2);
        }
        float2 o = unpack2(acc2);
        g_h[n * 64 + lane] = h0 + o.x;
        g_h[n * 64 + 32 + lane] = h1 + o.y;
    }
}

// ---------- launch ----------
extern "C" void kernel_launch(void* const* d_in, const int* in_sizes, int n_in,
                              void* d_out, int out_size) {
    const float* x   = (const float*)d_in[0];
    const int*   z   = (const int*)d_in[1];
    const float* t   = (const float*)d_in[2];
    const int*   ei  = (const int*)d_in[3];
    const float* emb = (const float*)d_in[4];
    const float* tw1 = (const float*)d_in[5];
    const float* tb1 = (const float*)d_in[6];
    const float* tw2 = (const float*)d_in[7];
    const float* tb2 = (const float*)d_in[8];
    const float* ew1 = (const float*)d_in[9];
    const float* eb1 = (const float*)d_in[10];
    const float* ew2 = (const float*)d_in[11];
    const float* eb2 = (const float*)d_in[12];
    const float* cw1 = (const float*)d_in[13];
    const float* cb1 = (const float*)d_in[14];
    const float* cw2 = (const float*)d_in[15];
    const float* cb2 = (const float*)d_in[16];
    const float* nw1 = (const float*)d_in[17];
    const float* nb1 = (const float*)d_in[18];
    const float* nw2 = (const float*)d_in[19];
    const float* nb2 = (const float*)d_in[20];
    float* out = (float*)d_out;
    const int B = in_sizes[2];

    float *pxA, *pxB, *pagg;
    cudaGetSymbolAddress((void**)&pxA, g_xA);
    cudaGetSymbolAddress((void**)&pxB, g_xB);
    cudaGetSymbolAddress((void**)&pagg, g_agg);

    cudaFuncSetAttribute(edge_kernel, cudaFuncAttributeMaxDynamicSharedMemorySize, ESMEM_BYTES);
    cudaFuncSetAttribute(node_kernel, cudaFuncAttributeMaxDynamicSharedMemorySize, NSMEM_BYTES);

    const int EBLK = 152;   // 1 block/SM on GB300 (152 SMs), ~199 KB smem each
    const int NBLK = 592;

    temb_kernel<<<1, 64>>>(t, tw1, tb1, tw2, tb2, B);
    init_h_kernel<<<(N_NODES * HID + 255) / 256, 256>>>(z, emb);
    cudaMemcpyAsync(pxA, x, (size_t)N_NODES * 3 * sizeof(float), cudaMemcpyDeviceToDevice, 0);

    // ---- layer 0 ----
    cudaMemsetAsync(pagg, 0, (size_t)N_NODES * HID * sizeof(float), 0);
    cudaMemcpyAsync(pxB, pxA, (size_t)N_NODES * 3 * sizeof(float), cudaMemcpyDeviceToDevice, 0);
    edge_kernel<<<EBLK, 512, ESMEM_BYTES>>>(pxA, pxB, ei,
        ew1 + 0 * 129 * 64, eb1 + 0 * 64, ew2 + 0 * 4096, eb2 + 0 * 64,
        cw1 + 0 * 4096, cb1 + 0 * 64, cw2 + 0 * 64, cb2 + 0, 1);
    node_kernel<<<NBLK, 256, NSMEM_BYTES>>>(nw1 + 0 * 128 * 64, nb1 + 0 * 64,
                                            nw2 + 0 * 4096, nb2 + 0 * 64);

    // ---- layer 1 ----
    cudaMemsetAsync(pagg, 0, (size_t)N_NODES * HID * sizeof(float), 0);
    cudaMemcpyAsync(pxA, pxB, (size_t)N_NODES * 3 * sizeof(float), cudaMemcpyDeviceToDevice, 0);
    edge_kernel<<<EBLK, 512, ESMEM_BYTES>>>(pxB, pxA, ei,
        ew1 + 1 * 129 * 64, eb1 + 1 * 64, ew2 + 1 * 4096, eb2 + 1 * 64,
        cw1 + 1 * 4096, cb1 + 1 * 64, cw2 + 1 * 64, cb2 + 1, 1);
    node_kernel<<<NBLK, 256, NSMEM_BYTES>>>(nw1 + 1 * 128 * 64, nb1 + 1 * 64,
                                            nw2 + 1 * 4096, nb2 + 1 * 64);

    // ---- layer 2: node MLP + agg dead, write x' straight to d_out ----
    cudaMemcpyAsync(out, pxA, (size_t)N_NODES * 3 * sizeof(float), cudaMemcpyDeviceToDevice, 0);
    edge_kernel<<<EBLK, 512, ESMEM_BYTES>>>(pxA, out, ei,
        ew1 + 2 * 129 * 64, eb1 + 2 * 64, ew2 + 2 * 4096, eb2 + 2 * 64,
        cw1 + 2 * 4096, cb1 + 2 * 64, cw2 + 2 * 64, cb2 + 2, 0);
}

// round 3
// speedup vs baseline: 2.4601x; 1.4664x over previous
#include <cuda_runtime.h>

#define N_NODES 100000
#define N_EDGES 1600000
#define HID 64
#define NGROUPS (N_EDGES / 32)       // 50000
#define NODE_GROUPS (N_NODES / 32)   // 3125

typedef unsigned long long ull;

// ---------- device scratch ----------
__device__ float g_h[N_NODES * HID];
__device__ float g_agg[N_NODES * HID];
__device__ float g_P[N_NODES * HID];
__device__ float g_Q[N_NODES * HID];
__device__ float g_xA[N_NODES * 3];
__device__ float g_xB[N_NODES * 3];

// ---------- helpers ----------
__device__ __forceinline__ ull ffma2(ull a, ull b, ull c) {
    ull d;
    asm("fma.rn.f32x2 %0, %1, %2, %3;" : "=l"(d) : "l"(a), "l"(b), "l"(c));
    return d;
}
__device__ __forceinline__ ull pack2(float x, float y) {
    ull r; asm("mov.b64 %0, {%1, %2};" : "=l"(r) : "f"(x), "f"(y)); return r;
}
__device__ __forceinline__ float2 unpack2(ull v) {
    float2 r; asm("mov.b64 {%0, %1}, %2;" : "=f"(r.x), "=f"(r.y) : "l"(v)); return r;
}
__device__ __forceinline__ float silu(float v) {
    return __fdividef(v, 1.0f + __expf(-v));
}
__device__ __forceinline__ void red_add_v4(float* addr, float a, float b, float c, float d) {
    asm volatile("red.global.add.v4.f32 [%0], {%1, %2, %3, %4};"
                 :: "l"(addr), "f"(a), "f"(b), "f"(c), "f"(d) : "memory");
}

// ---------- init: h = emb[z] + tmean (temb computed per block), agg = 0 ----------
__global__ void init_kernel(const int* __restrict__ z, const float* __restrict__ emb,
                            const float* __restrict__ t,
                            const float* __restrict__ tw1, const float* __restrict__ tb1,
                            const float* __restrict__ tw2, const float* __restrict__ tb2,
                            int B) {
    __shared__ float s1[HID];
    __shared__ float tm[HID];
    int tidb = threadIdx.x;
    if (tidb < HID) {
        float w = tw1[tidb], bb = tb1[tidb];
        float acc = 0.f;
        for (int b = 0; b < B; b++) acc += silu(t[b] * w + bb);
        s1[tidb] = acc / (float)B;
    }
    __syncthreads();
    if (tidb < HID) {
        float o = tb2[tidb];
        for (int k = 0; k < HID; k++) o += s1[k] * tw2[k * HID + tidb];
        tm[tidb] = o;
    }
    __syncthreads();
    int i = blockIdx.x * blockDim.x + tidb;
    if (i < N_NODES * HID) {
        int node = i >> 6, j = i & 63;
        g_h[i] = emb[z[node] * HID + j] + tm[j];
        g_agg[i] = 0.f;
    }
}

// ---------- precompute: P[n] = h[n]@W1a + b1, Q[n] = h[n]@W1b ----------
#define PRE_W1A 0
#define PRE_W1B 4096
#define PRE_B1  8192
#define PRE_FB  8256
#define PRE_SMEMF (PRE_FB + 12 * 32 * 97)
#define PRE_SMEM_BYTES (PRE_SMEMF * 4)

__global__ void __launch_bounds__(384, 1)
pre_kernel(const float* __restrict__ ew1, const float* __restrict__ eb1g) {
    extern __shared__ float sm[];
    int tid = threadIdx.x;
    for (int i = tid; i < 4096; i += 384) {
        int k = i >> 6, c = i & 63, q = c >> 2, r = c & 3;
        int j = 2 * q + (r >> 1) + ((r & 1) << 5);
        sm[PRE_W1A + i] = ew1[k * 64 + j];
        sm[PRE_W1B + i] = ew1[(64 + k) * 64 + j];
    }
    if (tid < 32) { sm[PRE_B1 + 2 * tid] = eb1g[tid]; sm[PRE_B1 + 2 * tid + 1] = eb1g[tid + 32]; }
    __syncthreads();
    const int lane = tid & 31, wrp = tid >> 5;
    float* fb = sm + PRE_FB + wrp * (32 * 97);
    const ulonglong2* WA = (const ulonglong2*)(sm + PRE_W1A);
    const ulonglong2* WB = (const ulonglong2*)(sm + PRE_W1B);
    const ull* B1 = (const ull*)(sm + PRE_B1);
    int gw = (blockIdx.x * 384 + tid) >> 5;
    int nwrp = (gridDim.x * 384) >> 5;
    for (int g = gw; g < NODE_GROUPS; g += nwrp) {
        const int base = g * 32;
        __syncwarp();
        #pragma unroll
        for (int c = 0; c < 2; c++) {
            int off = c << 5;
            #pragma unroll 8
            for (int e2 = 0; e2 < 32; e2++)
                fb[e2 * 97 + off + lane] = g_h[(base + e2) * 64 + off + lane];
        }
        __syncwarp();
        for (int pass = 0; pass < 2; pass++) {
            const ulonglong2* W = pass ? WB : WA;
            ull acc[32];
            #pragma unroll
            for (int i = 0; i < 32; i++) acc[i] = pass ? 0ull : B1[i];
            for (int k = 0; k < 64; k++) {
                float f = fb[lane * 97 + k];
                ull fd = pack2(f, f);
                #pragma unroll
                for (int q = 0; q < 16; q++) {
                    ulonglong2 wv = W[k * 16 + q];
                    acc[2 * q]     = ffma2(fd, wv.x, acc[2 * q]);
                    acc[2 * q + 1] = ffma2(fd, wv.y, acc[2 * q + 1]);
                }
            }
            float* dst = pass ? g_Q : g_P;
            __syncwarp();
            #pragma unroll
            for (int i = 0; i < 32; i++) fb[lane * 97 + 64 + i] = unpack2(acc[i]).x;
            __syncwarp();
            #pragma unroll 8
            for (int e2 = 0; e2 < 32; e2++)
                dst[(base + e2) * 64 + lane] = fb[e2 * 97 + 64 + lane];
            __syncwarp();
            #pragma unroll
            for (int i = 0; i < 32; i++) fb[lane * 97 + 64 + i] = unpack2(acc[i]).y;
            __syncwarp();
            #pragma unroll 8
            for (int e2 = 0; e2 < 32; e2++)
                dst[(base + e2) * 64 + 32 + lane] = fb[e2 * 97 + 64 + lane];
        }
    }
}

// ---------- edge kernel ----------
#define E_W2f   0
#define E_C1f   4096
#define E_W1C   8192
#define E_CW2   8256
#define E_B2f   8320
#define E_CB1   8384
#define E_CB2   8448
#define E_NIDX  8452
#define E_FB    (E_NIDX + 16 * 64)
#define E_SMEMF (E_FB + 16 * 32 * 65)
#define ESMEM_BYTES (E_SMEMF * 4)

__global__ void __launch_bounds__(512, 1)
edge_kernel(const float* __restrict__ x, float* __restrict__ xn,
            const int* __restrict__ ei,
            const float* __restrict__ w1c_g,
            const float* __restrict__ ew2, const float* __restrict__ eb2g,
            const float* __restrict__ cw1, const float* __restrict__ cb1g,
            const float* __restrict__ cw2, const float* __restrict__ cb2g,
            int do_agg) {
    extern __shared__ float sm[];
    const int tid = threadIdx.x;
    for (int i = tid; i < 4096; i += 512) {
        int k = i >> 6, c = i & 63, q = c >> 2, r = c & 3;
        int j = 2 * q + (r >> 1) + ((r & 1) << 5);
        sm[E_W2f + i] = ew2[k * 64 + j];
        sm[E_C1f + i] = cw1[k * 64 + j];
    }
    if (tid < 32) {
        sm[E_W1C + 2 * tid] = w1c_g[tid]; sm[E_W1C + 2 * tid + 1] = w1c_g[tid + 32];
        sm[E_CW2 + 2 * tid] = cw2[tid];   sm[E_CW2 + 2 * tid + 1] = cw2[tid + 32];
        sm[E_B2f + 2 * tid] = eb2g[tid];  sm[E_B2f + 2 * tid + 1] = eb2g[tid + 32];
        sm[E_CB1 + 2 * tid] = cb1g[tid];  sm[E_CB1 + 2 * tid + 1] = cb1g[tid + 32];
    }
    if (tid == 0) sm[E_CB2] = cb2g[0];
    __syncthreads();

    const int lane = tid & 31;
    const int wrp = tid >> 5;
    float* fb = sm + E_FB + wrp * (32 * 65);
    int* nidx = (int*)(sm + E_NIDX) + wrp * 64;
    const ulonglong2* W2v = (const ulonglong2*)(sm + E_W2f);
    const ulonglong2* C1v = (const ulonglong2*)(sm + E_C1f);
    const ull* W1C  = (const ull*)(sm + E_W1C);
    const ull* CW2v = (const ull*)(sm + E_CW2);
    const ull* B2v  = (const ull*)(sm + E_B2f);
    const ull* CB1v = (const ull*)(sm + E_CB1);
    const float cb2s = sm[E_CB2];

    const int gwarp = (blockIdx.x * 512 + tid) >> 5;
    const int nwarps = (gridDim.x * 512) >> 5;

    for (int g = gwarp; g < NGROUPS; g += nwarps) {
        const int e = g * 32 + lane;
        const int s = ei[e];
        const int d = ei[N_EDGES + e];
        const float dx0 = __ldg(&x[d * 3 + 0]) - __ldg(&x[s * 3 + 0]);
        const float dx1 = __ldg(&x[d * 3 + 1]) - __ldg(&x[s * 3 + 1]);
        const float dx2 = __ldg(&x[d * 3 + 2]) - __ldg(&x[s * 3 + 2]);
        const float r2 = dx0 * dx0 + dx1 * dx1 + dx2 * dx2;
        __syncwarp();                 // protect fb/nidx from previous iteration readers
        nidx[lane] = d;
        nidx[32 + lane] = s;
        __syncwarp();

        // ---- gather S = P[d] + Q[s] into fb rows (cols = outputs) ----
        #pragma unroll
        for (int c = 0; c < 2; c++) {
            int off = c << 5;
            #pragma unroll 8
            for (int e2 = 0; e2 < 32; e2++) {
                int nd = nidx[e2];
                fb[e2 * 65 + off + lane] = __ldg(&g_P[nd * 64 + off + lane]);
            }
        }
        #pragma unroll
        for (int c = 0; c < 2; c++) {
            int off = c << 5;
            #pragma unroll 8
            for (int e2 = 0; e2 < 32; e2++) {
                int ns = nidx[32 + e2];
                fb[e2 * 65 + off + lane] += __ldg(&g_Q[ns * 64 + off + lane]);
            }
        }
        __syncwarp();

        // ---- phase 1 (elementwise now): ef1 = silu(S + r2 * w1c) ----
        #pragma unroll
        for (int i = 0; i < 32; i++) {
            float2 w = unpack2(W1C[i]);
            float f0 = fb[lane * 65 + i];
            float f1 = fb[lane * 65 + 32 + i];
            fb[lane * 65 + i]      = silu(fmaf(r2, w.x, f0));
            fb[lane * 65 + 32 + i] = silu(fmaf(r2, w.y, f1));
        }

        // ---- phase 2: @ W2 -> m = silu ----
        ull acc[32];
        #pragma unroll
        for (int i = 0; i < 32; i++) acc[i] = B2v[i];
        for (int k = 0; k < 64; k++) {
            float f = fb[lane * 65 + k];
            ull fd = pack2(f, f);
            #pragma unroll
            for (int q = 0; q < 16; q++) {
                ulonglong2 wv = W2v[k * 16 + q];
                acc[2 * q]     = ffma2(fd, wv.x, acc[2 * q]);
                acc[2 * q + 1] = ffma2(fd, wv.y, acc[2 * q + 1]);
            }
        }
        // m epilogue: silu, store to own row, vector red for agg
        #pragma unroll
        for (int t = 0; t < 8; t++) {
            float2 a0 = unpack2(acc[4 * t + 0]);
            float2 a1 = unpack2(acc[4 * t + 1]);
            float2 a2 = unpack2(acc[4 * t + 2]);
            float2 a3 = unpack2(acc[4 * t + 3]);
            float l0 = silu(a0.x), l1 = silu(a1.x), l2 = silu(a2.x), l3 = silu(a3.x);
            float h0 = silu(a0.y), h1 = silu(a1.y), h2 = silu(a2.y), h3 = silu(a3.y);
            fb[lane * 65 + 4 * t + 0] = l0;
            fb[lane * 65 + 4 * t + 1] = l1;
            fb[lane * 65 + 4 * t + 2] = l2;
            fb[lane * 65 + 4 * t + 3] = l3;
            fb[lane * 65 + 32 + 4 * t + 0] = h0;
            fb[lane * 65 + 32 + 4 * t + 1] = h1;
            fb[lane * 65 + 32 + 4 * t + 2] = h2;
            fb[lane * 65 + 32 + 4 * t + 3] = h3;
            if (do_agg) {
                red_add_v4(&g_agg[d * 64 + 4 * t], l0, l1, l2, l3);
                red_add_v4(&g_agg[d * 64 + 32 + 4 * t], h0, h1, h2, h3);
            }
        }

        // ---- phase 3: coord MLP hidden ----
        #pragma unroll
        for (int i = 0; i < 32; i++) acc[i] = CB1v[i];
        for (int k = 0; k < 64; k++) {
            float f = fb[lane * 65 + k];
            ull fd = pack2(f, f);
            #pragma unroll
            for (int q = 0; q < 16; q++) {
                ulonglong2 wv = C1v[k * 16 + q];
                acc[2 * q]     = ffma2(fd, wv.x, acc[2 * q]);
                acc[2 * q + 1] = ffma2(fd, wv.y, acc[2 * q + 1]);
            }
        }
        float p = cb2s;
        #pragma unroll
        for (int i = 0; i < 32; i++) {
            float2 a = unpack2(acc[i]);
            float2 wv = unpack2(CW2v[i]);
            p = fmaf(silu(a.x), wv.x, p);
            p = fmaf(silu(a.y), wv.y, p);
        }
        atomicAdd(&xn[d * 3 + 0], dx0 * p);
        atomicAdd(&xn[d * 3 + 1], dx1 * p);
        atomicAdd(&xn[d * 3 + 2], dx2 * p);
    }
}

// ---------- node kernel (lane=node): h += MLP([h, agg]), agg = 0 ----------
#define N_W1  0
#define N_W2  8192
#define N_B1  12288
#define N_B2  12352
#define N_FB  12416
#define N_SMEMF (N_FB + 12 * 32 * 65)
#define NSMEM_BYTES (N_SMEMF * 4)

__global__ void __launch_bounds__(384, 1)
node_kernel(const float* __restrict__ nw1, const float* __restrict__ nb1g,
            const float* __restrict__ nw2, const float* __restrict__ nb2g) {
    extern __shared__ float sm[];
    int tid = threadIdx.x;
    for (int i = tid; i < 8192; i += 384) {
        int k = i >> 6, c = i & 63, q = c >> 2, r = c & 3;
        int j = 2 * q + (r >> 1) + ((r & 1) << 5);
        sm[N_W1 + i] = nw1[k * 64 + j];
    }
    for (int i = tid; i < 4096; i += 384) {
        int k = i >> 6, c = i & 63, q = c >> 2, r = c & 3;
        int j = 2 * q + (r >> 1) + ((r & 1) << 5);
        sm[N_W2 + i] = nw2[k * 64 + j];
    }
    if (tid < 32) {
        sm[N_B1 + 2 * tid] = nb1g[tid]; sm[N_B1 + 2 * tid + 1] = nb1g[tid + 32];
        sm[N_B2 + 2 * tid] = nb2g[tid]; sm[N_B2 + 2 * tid + 1] = nb2g[tid + 32];
    }
    __syncthreads();
    const int lane = tid & 31, wrp = tid >> 5;
    float* fb = sm + N_FB + wrp * (32 * 65);
    const ulonglong2* W1 = (const ulonglong2*)(sm + N_W1);
    const ulonglong2* W2 = (const ulonglong2*)(sm + N_W2);
    const ull* B1 = (const ull*)(sm + N_B1);
    const ull* B2 = (const ull*)(sm + N_B2);
    int gw = (blockIdx.x * 384 + tid) >> 5;
    int nwrp = (gridDim.x * 384) >> 5;
    for (int g = gw; g < NODE_GROUPS; g += nwrp) {
        const int base = g * 32;
        ull acc[32];
        #pragma unroll
        for (int i = 0; i < 32; i++) acc[i] = B1[i];
        for (int c = 0; c < 4; c++) {
            const float* src = (c < 2) ? g_h : g_agg;
            int off = (c & 1) << 5;
            __syncwarp();
            #pragma unroll 8
            for (int e2 = 0; e2 < 32; e2++)
                fb[e2 * 65 + lane] = src[(base + e2) * 64 + off + lane];
            __syncwarp();
            const ulonglong2* Wk = W1 + (c * 32) * 16;
            for (int k = 0; k < 32; k++) {
                float f = fb[lane * 65 + k];
                ull fd = pack2(f, f);
                #pragma unroll
                for (int q = 0; q < 16; q++) {
                    ulonglong2 wv = Wk[k * 16 + q];
                    acc[2 * q]     = ffma2(fd, wv.x, acc[2 * q]);
                    acc[2 * q + 1] = ffma2(fd, wv.y, acc[2 * q + 1]);
                }
            }
        }
        __syncwarp();
        #pragma unroll
        for (int i = 0; i < 32; i++) {
            float2 a = unpack2(acc[i]);
            fb[lane * 65 + i]      = silu(a.x);
            fb[lane * 65 + 32 + i] = silu(a.y);
        }
        #pragma unroll
        for (int i = 0; i < 32; i++) acc[i] = B2[i];
        for (int k = 0; k < 64; k++) {
            float f = fb[lane * 65 + k];
            ull fd = pack2(f, f);
            #pragma unroll
            for (int q = 0; q < 16; q++) {
                ulonglong2 wv = W2[k * 16 + q];
                acc[2 * q]     = ffma2(fd, wv.x, acc[2 * q]);
                acc[2 * q + 1] = ffma2(fd, wv.y, acc[2 * q + 1]);
            }
        }
        // residual writeback + agg zero (transpose via fb, 2 chunks)
        __syncwarp();
        #pragma unroll
        for (int i = 0; i < 32; i++) fb[lane * 65 + i] = unpack2(acc[i]).x;
        __syncwarp();
        #pragma unroll 8
        for (int e2 = 0; e2 < 32; e2++) {
            int idx = (base + e2) * 64 + lane;
            g_h[idx] += fb[e2 * 65 + lane];
            g_agg[idx] = 0.f;
        }
        __syncwarp();
        #pragma unroll
        for (int i = 0; i < 32; i++) fb[lane * 65 + i] = unpack2(acc[i]).y;
        __syncwarp();
        #pragma unroll 8
        for (int e2 = 0; e2 < 32; e2++) {
            int idx = (base + e2) * 64 + 32 + lane;
            g_h[idx] += fb[e2 * 65 + lane];
            g_agg[idx] = 0.f;
        }
    }
}

// ---------- launch ----------
extern "C" void kernel_launch(void* const* d_in, const int* in_sizes, int n_in,
                              void* d_out, int out_size) {
    const float* x   = (const float*)d_in[0];
    const int*   z   = (const int*)d_in[1];
    const float* t   = (const float*)d_in[2];
    const int*   ei  = (const int*)d_in[3];
    const float* emb = (const float*)d_in[4];
    const float* tw1 = (const float*)d_in[5];
    const float* tb1 = (const float*)d_in[6];
    const float* tw2 = (const float*)d_in[7];
    const float* tb2 = (const float*)d_in[8];
    const float* ew1 = (const float*)d_in[9];
    const float* eb1 = (const float*)d_in[10];
    const float* ew2 = (const float*)d_in[11];
    const float* eb2 = (const float*)d_in[12];
    const float* cw1 = (const float*)d_in[13];
    const float* cb1 = (const float*)d_in[14];
    const float* cw2 = (const float*)d_in[15];
    const float* cb2 = (const float*)d_in[16];
    const float* nw1 = (const float*)d_in[17];
    const float* nb1 = (const float*)d_in[18];
    const float* nw2 = (const float*)d_in[19];
    const float* nb2 = (const float*)d_in[20];
    float* out = (float*)d_out;
    const int B = in_sizes[2];

    float *pxA, *pxB;
    cudaGetSymbolAddress((void**)&pxA, g_xA);
    cudaGetSymbolAddress((void**)&pxB, g_xB);

    cudaFuncSetAttribute(edge_kernel, cudaFuncAttributeMaxDynamicSharedMemorySize, ESMEM_BYTES);
    cudaFuncSetAttribute(node_kernel, cudaFuncAttributeMaxDynamicSharedMemorySize, NSMEM_BYTES);
    cudaFuncSetAttribute(pre_kernel,  cudaFuncAttributeMaxDynamicSharedMemorySize, PRE_SMEM_BYTES);

    const size_t XB = (size_t)N_NODES * 3 * sizeof(float);

    // kernel launch order (memcpys are graph memcpy nodes, not kernel launches):
    // 0:init 1:pre0 2:edge0 3:node0 4:pre1 5:edge1 6:node1 7:pre2 8:edge2
    init_kernel<<<(N_NODES * HID + 255) / 256, 256>>>(z, emb, t, tw1, tb1, tw2, tb2, B);

    // ---- layer 0: x_in = x (input), x_out accumulates in xB = copy(x) ----
    pre_kernel<<<152, 384, PRE_SMEM_BYTES>>>(ew1 + 0 * 129 * 64, eb1 + 0 * 64);
    cudaMemcpyAsync(pxB, x, XB, cudaMemcpyDeviceToDevice, 0);
    edge_kernel<<<152, 512, ESMEM_BYTES>>>(x, pxB, ei,
        ew1 + 0 * 129 * 64 + 128 * 64, ew2 + 0 * 4096, eb2 + 0 * 64,
        cw1 + 0 * 4096, cb1 + 0 * 64, cw2 + 0 * 64, cb2 + 0, 1);
    node_kernel<<<152, 384, NSMEM_BYTES>>>(nw1 + 0 * 128 * 64, nb1 + 0 * 64,
                                           nw2 + 0 * 4096, nb2 + 0 * 64);

    // ---- layer 1: x in xB, x' in xA ----
    pre_kernel<<<152, 384, PRE_SMEM_BYTES>>>(ew1 + 1 * 129 * 64, eb1 + 1 * 64);
    cudaMemcpyAsync(pxA, pxB, XB, cudaMemcpyDeviceToDevice, 0);
    edge_kernel<<<152, 512, ESMEM_BYTES>>>(pxB, pxA, ei,
        ew1 + 1 * 129 * 64 + 128 * 64, ew2 + 1 * 4096, eb2 + 1 * 64,
        cw1 + 1 * 4096, cb1 + 1 * 64, cw2 + 1 * 64, cb2 + 1, 1);
    node_kernel<<<152, 384, NSMEM_BYTES>>>(nw1 + 1 * 128 * 64, nb1 + 1 * 64,
                                           nw2 + 1 * 4096, nb2 + 1 * 64);

    // ---- layer 2: x in xA, x' -> d_out; agg/node dead ----
    pre_kernel<<<152, 384, PRE_SMEM_BYTES>>>(ew1 + 2 * 129 * 64, eb1 + 2 * 64);
    cudaMemcpyAsync(out, pxA, XB, cudaMemcpyDeviceToDevice, 0);
    edge_kernel<<<152, 512, ESMEM_BYTES>>>(pxA, out, ei,
        ew1 + 2 * 129 * 64 + 128 * 64, ew2 + 2 * 4096, eb2 + 2 * 64,
        cw1 + 2 * 4096, cb1 + 2 * 64, cw2 + 2 * 64, cb2 + 2, 0);
}

// round 4
// speedup vs baseline: 3.1487x; 1.2799x over previous
#include <cuda_runtime.h>

#define N_NODES 100000
#define N_EDGES 1600000
#define HID 64
#define NGROUPS (N_EDGES / 32)       // 50000
#define NODE_GROUPS (N_NODES / 32)   // 3125

typedef unsigned long long ull;

// ---------- device scratch ----------
__device__ float g_h[N_NODES * HID];
__device__ float g_agg[N_NODES * HID];
__device__ float g_P[N_NODES * HID];
__device__ float g_Q[N_NODES * HID];
__device__ float g_xA[N_NODES * 3];
__device__ float g_xB[N_NODES * 3];

// ---------- helpers ----------
__device__ __forceinline__ ull ffma2(ull a, ull b, ull c) {
    ull d;
    asm("fma.rn.f32x2 %0, %1, %2, %3;" : "=l"(d) : "l"(a), "l"(b), "l"(c));
    return d;
}
__device__ __forceinline__ ull pack2(float x, float y) {
    ull r; asm("mov.b64 %0, {%1, %2};" : "=l"(r) : "f"(x), "f"(y)); return r;
}
__device__ __forceinline__ float2 unpack2(ull v) {
    float2 r; asm("mov.b64 {%0, %1}, %2;" : "=f"(r.x), "=f"(r.y) : "l"(v)); return r;
}
__device__ __forceinline__ float silu(float v) {
    return __fdividef(v, 1.0f + __expf(-v));
}
__device__ __forceinline__ void red_add_v4(float* addr, float a, float b, float c, float d) {
    asm volatile("red.global.add.v4.f32 [%0], {%1, %2, %3, %4};"
                 :: "l"(addr), "f"(a), "f"(b), "f"(c), "f"(d) : "memory");
}

// 16-accumulator matmul pass: 64 k-steps, 8 weight quads per k.
// W points at the pass's quad base (quad stride per k is 16).
__device__ __forceinline__ void mm_pass16(const float* __restrict__ frow,
                                          const ulonglong2* __restrict__ W,
                                          ull acc[16]) {
    #pragma unroll 4
    for (int k = 0; k < 64; k++) {
        float f = frow[k];
        ull fd = pack2(f, f);
        #pragma unroll
        for (int q = 0; q < 8; q++) {
            ulonglong2 wv = W[k * 16 + q];
            acc[2 * q]     = ffma2(fd, wv.x, acc[2 * q]);
            acc[2 * q + 1] = ffma2(fd, wv.y, acc[2 * q + 1]);
        }
    }
}

// quad-pair weight staging: dest[k*64 + 4q + r] = w[k][2q + (r>>1) + ((r&1)<<5)]
__device__ __forceinline__ void stage_quad(float* dst, const float* __restrict__ src,
                                           int rows, int tid, int nthreads) {
    for (int i = tid; i < rows * 64; i += nthreads) {
        int k = i >> 6, c = i & 63, q = c >> 2, r = c & 3;
        int j = 2 * q + (r >> 1) + ((r & 1) << 5);
        dst[i] = src[k * 64 + j];
    }
}

// ---------- init: h = emb[z] + tmean, agg = 0 ----------
__global__ void init_kernel(const int* __restrict__ z, const float* __restrict__ emb,
                            const float* __restrict__ t,
                            const float* __restrict__ tw1, const float* __restrict__ tb1,
                            const float* __restrict__ tw2, const float* __restrict__ tb2,
                            int B) {
    __shared__ float s1[HID];
    __shared__ float tm[HID];
    int tidb = threadIdx.x;
    if (tidb < HID) {
        float w = tw1[tidb], bb = tb1[tidb];
        float acc = 0.f;
        for (int b = 0; b < B; b++) acc += silu(t[b] * w + bb);
        s1[tidb] = acc / (float)B;
    }
    __syncthreads();
    if (tidb < HID) {
        float o = tb2[tidb];
        for (int k = 0; k < HID; k++) o += s1[k] * tw2[k * HID + tidb];
        tm[tidb] = o;
    }
    __syncthreads();
    int i = blockIdx.x * blockDim.x + tidb;
    if (i < N_NODES * HID) {
        int node = i >> 6, j = i & 63;
        g_h[i] = emb[z[node] * HID + j] + tm[j];
        g_agg[i] = 0.f;
    }
}

// ---------- pre kernel: P = h@W1a + b1, Q = h@W1b ----------
#define P_WA   0
#define P_WB   4096
#define P_B1   8192
#define P_WARP 8256
#define P_PW   (32 * 65)
#define P_SMEMF (P_WARP + 16 * P_PW)
#define P_SMEM_BYTES (P_SMEMF * 4)

__global__ void __launch_bounds__(512, 1)
pre_kernel(const float* __restrict__ ew1, const float* __restrict__ eb1g) {
    extern __shared__ float sm[];
    const int tid = threadIdx.x;
    stage_quad(sm + P_WA, ew1, 64, tid, 512);
    stage_quad(sm + P_WB, ew1 + 64 * 64, 64, tid, 512);
    if (tid < 32) { sm[P_B1 + 2 * tid] = eb1g[tid]; sm[P_B1 + 2 * tid + 1] = eb1g[tid + 32]; }
    __syncthreads();

    const int lane = tid & 31, wrp = tid >> 5;
    float* fb = sm + P_WARP + wrp * P_PW;
    float* frow = fb + lane * 65;
    const ulonglong2* WA = (const ulonglong2*)(sm + P_WA);
    const ulonglong2* WB = (const ulonglong2*)(sm + P_WB);
    const ull* B1 = (const ull*)(sm + P_B1);

    int gw = (blockIdx.x * 512 + tid) >> 5;
    int nwrp = (gridDim.x * 512) >> 5;
    for (int g = gw; g < NODE_GROUPS; g += nwrp) {
        const int base = g * 32;
        __syncwarp();
        #pragma unroll 4
        for (int e2 = 0; e2 < 32; e2++) {
            float2 hv = *(const float2*)(g_h + (size_t)(base + e2) * 64 + 2 * lane);
            fb[e2 * 65 + 2 * lane] = hv.x;
            fb[e2 * 65 + 2 * lane + 1] = hv.y;
        }
        __syncwarp();
        float* dstP = g_P + (size_t)(base + lane) * 64;
        float* dstQ = g_Q + (size_t)(base + lane) * 64;
        #pragma unroll
        for (int mat = 0; mat < 2; mat++) {
            const ulonglong2* W = mat ? WB : WA;
            float* dst = mat ? dstQ : dstP;
            #pragma unroll
            for (int pass = 0; pass < 2; pass++) {
                ull acc[16];
                #pragma unroll
                for (int a = 0; a < 16; a++) acc[a] = mat ? 0ull : B1[16 * pass + a];
                mm_pass16(frow, W + 8 * pass, acc);
                #pragma unroll
                for (int t4 = 0; t4 < 4; t4++) {
                    float2 v0 = unpack2(acc[4 * t4 + 0]);
                    float2 v1 = unpack2(acc[4 * t4 + 1]);
                    float2 v2 = unpack2(acc[4 * t4 + 2]);
                    float2 v3 = unpack2(acc[4 * t4 + 3]);
                    float4 lo = make_float4(v0.x, v1.x, v2.x, v3.x);
                    float4 hi = make_float4(v0.y, v1.y, v2.y, v3.y);
                    *(float4*)(dst + 16 * pass + 4 * t4) = lo;
                    *(float4*)(dst + 16 * pass + 32 + 4 * t4) = hi;
                }
            }
        }
    }
}

// ---------- edge kernel ----------
#define E_W2f   0
#define E_C1f   4096
#define E_CW2   8192
#define E_B2f   8256
#define E_CB1   8320
#define E_CB2   8384
#define E_WARP  8388
#define E_PW    (96 + 32 * 65)      // idxd32 idxs32 r2s32 + fb
#define E_SMEMF (E_WARP + 16 * E_PW)
#define ESMEM_BYTES (E_SMEMF * 4)

__global__ void __launch_bounds__(512, 1)
edge_kernel(const float* __restrict__ x, float* __restrict__ xn,
            const int* __restrict__ ei,
            const float* __restrict__ w1c_g,
            const float* __restrict__ ew2, const float* __restrict__ eb2g,
            const float* __restrict__ cw1, const float* __restrict__ cb1g,
            const float* __restrict__ cw2, const float* __restrict__ cb2g,
            int do_agg) {
    extern __shared__ float sm[];
    const int tid = threadIdx.x;
    stage_quad(sm + E_W2f, ew2, 64, tid, 512);
    stage_quad(sm + E_C1f, cw1, 64, tid, 512);
    if (tid < 32) {
        sm[E_CW2 + 2 * tid] = cw2[tid];   sm[E_CW2 + 2 * tid + 1] = cw2[tid + 32];
        sm[E_B2f + 2 * tid] = eb2g[tid];  sm[E_B2f + 2 * tid + 1] = eb2g[tid + 32];
        sm[E_CB1 + 2 * tid] = cb1g[tid];  sm[E_CB1 + 2 * tid + 1] = cb1g[tid + 32];
    }
    if (tid == 0) sm[E_CB2] = cb2g[0];
    __syncthreads();

    const int lane = tid & 31, wrp = tid >> 5;
    float* wb = sm + E_WARP + wrp * E_PW;
    int* idxd = (int*)wb;
    int* idxs = idxd + 32;
    float* r2s = wb + 64;
    float* fb = wb + 96;
    float* frow = fb + lane * 65;
    const ulonglong2* W2v = (const ulonglong2*)(sm + E_W2f);
    const ulonglong2* C1v = (const ulonglong2*)(sm + E_C1f);
    const ull* CW2v = (const ull*)(sm + E_CW2);
    const ull* B2v  = (const ull*)(sm + E_B2f);
    const ull* CB1v = (const ull*)(sm + E_CB1);
    const float cb2s = sm[E_CB2];
    const float w1c0 = __ldg(&w1c_g[2 * lane]);
    const float w1c1 = __ldg(&w1c_g[2 * lane + 1]);

    const int gwarp = (blockIdx.x * 512 + tid) >> 5;
    const int nwarps = (gridDim.x * 512) >> 5;

    for (int g = gwarp; g < NGROUPS; g += nwarps) {
        const int e = g * 32 + lane;
        const int s = ei[e];
        const int d = ei[N_EDGES + e];
        const float dx0 = __ldg(&x[d * 3 + 0]) - __ldg(&x[s * 3 + 0]);
        const float dx1 = __ldg(&x[d * 3 + 1]) - __ldg(&x[s * 3 + 1]);
        const float dx2 = __ldg(&x[d * 3 + 2]) - __ldg(&x[s * 3 + 2]);
        const float r2 = dx0 * dx0 + dx1 * dx1 + dx2 * dx2;
        __syncwarp();                      // prior iteration done with wb
        idxd[lane] = d; idxs[lane] = s; r2s[lane] = r2;
        __syncwarp();

        // ---- gather + phase-1 fused: fb[e2][j] = silu(P[d_e2][j] + Q[s_e2][j] + r2_e2 * w1c[j]) ----
        #pragma unroll 4
        for (int e2 = 0; e2 < 32; e2++) {
            int nd = idxd[e2], ns = idxs[e2];
            float rr = r2s[e2];
            float2 pv = *(const float2*)(g_P + (size_t)nd * 64 + 2 * lane);
            float2 qv = *(const float2*)(g_Q + (size_t)ns * 64 + 2 * lane);
            fb[e2 * 65 + 2 * lane]     = silu(fmaf(rr, w1c0, pv.x + qv.x));
            fb[e2 * 65 + 2 * lane + 1] = silu(fmaf(rr, w1c1, pv.y + qv.y));
        }
        __syncwarp();

        // ---- phase 2: m = silu(ef1 @ W2 + b2), two output passes ----
        ull acc[16];
        float mlo[16], mhi[16];
        #pragma unroll
        for (int a = 0; a < 16; a++) acc[a] = B2v[a];
        mm_pass16(frow, W2v, acc);
        #pragma unroll
        for (int a = 0; a < 16; a++) {
            float2 v = unpack2(acc[a]);
            mlo[a] = silu(v.x); mhi[a] = silu(v.y);
        }
        if (do_agg) {
            #pragma unroll
            for (int t4 = 0; t4 < 4; t4++) {
                red_add_v4(&g_agg[(size_t)d * 64 + 4 * t4], mlo[4*t4], mlo[4*t4+1], mlo[4*t4+2], mlo[4*t4+3]);
                red_add_v4(&g_agg[(size_t)d * 64 + 32 + 4 * t4], mhi[4*t4], mhi[4*t4+1], mhi[4*t4+2], mhi[4*t4+3]);
            }
        }
        #pragma unroll
        for (int a = 0; a < 16; a++) acc[a] = B2v[16 + a];
        mm_pass16(frow, W2v + 8, acc);
        {
            float nlo[16], nhi[16];
            #pragma unroll
            for (int a = 0; a < 16; a++) {
                float2 v = unpack2(acc[a]);
                nlo[a] = silu(v.x); nhi[a] = silu(v.y);
            }
            if (do_agg) {
                #pragma unroll
                for (int t4 = 0; t4 < 4; t4++) {
                    red_add_v4(&g_agg[(size_t)d * 64 + 16 + 4 * t4], nlo[4*t4], nlo[4*t4+1], nlo[4*t4+2], nlo[4*t4+3]);
                    red_add_v4(&g_agg[(size_t)d * 64 + 48 + 4 * t4], nhi[4*t4], nhi[4*t4+1], nhi[4*t4+2], nhi[4*t4+3]);
                }
            }
            // write m into own row (safe: each lane owns its row)
            #pragma unroll
            for (int a = 0; a < 16; a++) { frow[16 + a] = nlo[a]; frow[48 + a] = nhi[a]; }
        }
        #pragma unroll
        for (int a = 0; a < 16; a++) { frow[a] = mlo[a]; frow[32 + a] = mhi[a]; }

        // ---- phase 3: cw = silu(m @ C1 + cb1) . cw2 + cb2, two passes ----
        float p = cb2s;
        #pragma unroll
        for (int pass = 0; pass < 2; pass++) {
            #pragma unroll
            for (int a = 0; a < 16; a++) acc[a] = CB1v[16 * pass + a];
            mm_pass16(frow, C1v + 8 * pass, acc);
            #pragma unroll
            for (int a = 0; a < 16; a++) {
                float2 v = unpack2(acc[a]);
                float2 cwv = unpack2(CW2v[16 * pass + a]);
                p = fmaf(silu(v.x), cwv.x, p);
                p = fmaf(silu(v.y), cwv.y, p);
            }
        }
        atomicAdd(&xn[d * 3 + 0], dx0 * p);
        atomicAdd(&xn[d * 3 + 1], dx1 * p);
        atomicAdd(&xn[d * 3 + 2], dx2 * p);
    }
}

// ---------- node kernel: h += MLP([h, agg]) @ residual, agg = 0 ----------
#define ND_W1   0
#define ND_W2   8192
#define ND_B1   12288
#define ND_B2   12352
#define ND_WARP 12416
#define ND_PW   (32 * 65)
#define ND_SMEMF (ND_WARP + 16 * ND_PW)
#define NSMEM_BYTES (ND_SMEMF * 4)

__global__ void __launch_bounds__(512, 1)
node_kernel(const float* __restrict__ nw1, const float* __restrict__ nb1g,
            const float* __restrict__ nw2, const float* __restrict__ nb2g) {
    extern __shared__ float sm[];
    const int tid = threadIdx.x;
    stage_quad(sm + ND_W1, nw1, 128, tid, 512);
    stage_quad(sm + ND_W2, nw2, 64, tid, 512);
    if (tid < 32) {
        sm[ND_B1 + 2 * tid] = nb1g[tid]; sm[ND_B1 + 2 * tid + 1] = nb1g[tid + 32];
        sm[ND_B2 + 2 * tid] = nb2g[tid]; sm[ND_B2 + 2 * tid + 1] = nb2g[tid + 32];
    }
    __syncthreads();

    const int lane = tid & 31, wrp = tid >> 5;
    float* fb = sm + ND_WARP + wrp * ND_PW;
    float* frow = fb + lane * 65;
    const ulonglong2* W1v = (const ulonglong2*)(sm + ND_W1);
    const ulonglong2* W2v = (const ulonglong2*)(sm + ND_W2);
    const ull* B1 = (const ull*)(sm + ND_B1);
    const ull* B2 = (const ull*)(sm + ND_B2);

    int gw = (blockIdx.x * 512 + tid) >> 5;
    int nwrp = (gridDim.x * 512) >> 5;
    for (int g = gw; g < NODE_GROUPS; g += nwrp) {
        const int base = g * 32;
        ull acc[16];
        float mlo[16], mhi[16];
        // ---- matmul1 pass 0 (outputs 0..15, 32..47) ----
        #pragma unroll
        for (int a = 0; a < 16; a++) acc[a] = B1[a];
        __syncwarp();
        #pragma unroll 4
        for (int e2 = 0; e2 < 32; e2++) {
            float2 hv = *(const float2*)(g_h + (size_t)(base + e2) * 64 + 2 * lane);
            fb[e2 * 65 + 2 * lane] = hv.x; fb[e2 * 65 + 2 * lane + 1] = hv.y;
        }
        __syncwarp();
        mm_pass16(frow, W1v, acc);                 // rows 0..63
        __syncwarp();
        #pragma unroll 4
        for (int e2 = 0; e2 < 32; e2++) {
            float2 av = *(const float2*)(g_agg + (size_t)(base + e2) * 64 + 2 * lane);
            fb[e2 * 65 + 2 * lane] = av.x; fb[e2 * 65 + 2 * lane + 1] = av.y;
        }
        __syncwarp();
        mm_pass16(frow, W1v + 64 * 16, acc);       // rows 64..127
        #pragma unroll
        for (int a = 0; a < 16; a++) {
            float2 v = unpack2(acc[a]);
            mlo[a] = silu(v.x); mhi[a] = silu(v.y);
        }
        // ---- matmul1 pass 1 (outputs 16..31, 48..63) ----
        #pragma unroll
        for (int a = 0; a < 16; a++) acc[a] = B1[16 + a];
        __syncwarp();
        #pragma unroll 4
        for (int e2 = 0; e2 < 32; e2++) {
            float2 hv = *(const float2*)(g_h + (size_t)(base + e2) * 64 + 2 * lane);
            fb[e2 * 65 + 2 * lane] = hv.x; fb[e2 * 65 + 2 * lane + 1] = hv.y;
        }
        __syncwarp();
        mm_pass16(frow, W1v + 8, acc);
        __syncwarp();
        #pragma unroll 4
        for (int e2 = 0; e2 < 32; e2++) {
            float2 av = *(const float2*)(g_agg + (size_t)(base + e2) * 64 + 2 * lane);
            fb[e2 * 65 + 2 * lane] = av.x; fb[e2 * 65 + 2 * lane + 1] = av.y;
        }
        __syncwarp();
        mm_pass16(frow, W1v + 64 * 16 + 8, acc);
        // hidden -> own row
        #pragma unroll
        for (int a = 0; a < 16; a++) {
            float2 v = unpack2(acc[a]);
            frow[16 + a] = silu(v.x); frow[48 + a] = silu(v.y);
        }
        #pragma unroll
        for (int a = 0; a < 16; a++) { frow[a] = mlo[a]; frow[32 + a] = mhi[a]; }

        // ---- matmul2 + residual + agg zero ----
        float* hrow = g_h + (size_t)(base + lane) * 64;
        float* arow = g_agg + (size_t)(base + lane) * 64;
        #pragma unroll
        for (int pass = 0; pass < 2; pass++) {
            #pragma unroll
            for (int a = 0; a < 16; a++) acc[a] = B2[16 * pass + a];
            mm_pass16(frow, W2v + 8 * pass, acc);
            #pragma unroll
            for (int t4 = 0; t4 < 4; t4++) {
                float2 v0 = unpack2(acc[4 * t4 + 0]);
                float2 v1 = unpack2(acc[4 * t4 + 1]);
                float2 v2 = unpack2(acc[4 * t4 + 2]);
                float2 v3 = unpack2(acc[4 * t4 + 3]);
                float4 ho = *(const float4*)(hrow + 16 * pass + 4 * t4);
                ho.x += v0.x; ho.y += v1.x; ho.z += v2.x; ho.w += v3.x;
                *(float4*)(hrow + 16 * pass + 4 * t4) = ho;
                float4 hh = *(const float4*)(hrow + 16 * pass + 32 + 4 * t4);
                hh.x += v0.y; hh.y += v1.y; hh.z += v2.y; hh.w += v3.y;
                *(float4*)(hrow + 16 * pass + 32 + 4 * t4) = hh;
                *(float4*)(arow + 16 * pass + 4 * t4) = make_float4(0.f, 0.f, 0.f, 0.f);
                *(float4*)(arow + 16 * pass + 32 + 4 * t4) = make_float4(0.f, 0.f, 0.f, 0.f);
            }
        }
    }
}

// ---------- launch ----------
extern "C" void kernel_launch(void* const* d_in, const int* in_sizes, int n_in,
                              void* d_out, int out_size) {
    const float* x   = (const float*)d_in[0];
    const int*   z   = (const int*)d_in[1];
    const float* t   = (const float*)d_in[2];
    const int*   ei  = (const int*)d_in[3];
    const float* emb = (const float*)d_in[4];
    const float* tw1 = (const float*)d_in[5];
    const float* tb1 = (const float*)d_in[6];
    const float* tw2 = (const float*)d_in[7];
    const float* tb2 = (const float*)d_in[8];
    const float* ew1 = (const float*)d_in[9];
    const float* eb1 = (const float*)d_in[10];
    const float* ew2 = (const float*)d_in[11];
    const float* eb2 = (const float*)d_in[12];
    const float* cw1 = (const float*)d_in[13];
    const float* cb1 = (const float*)d_in[14];
    const float* cw2 = (const float*)d_in[15];
    const float* cb2 = (const float*)d_in[16];
    const float* nw1 = (const float*)d_in[17];
    const float* nb1 = (const float*)d_in[18];
    const float* nw2 = (const float*)d_in[19];
    const float* nb2 = (const float*)d_in[20];
    float* out = (float*)d_out;
    const int B = in_sizes[2];

    float *pxA, *pxB;
    cudaGetSymbolAddress((void**)&pxA, g_xA);
    cudaGetSymbolAddress((void**)&pxB, g_xB);

    cudaFuncSetAttribute(edge_kernel, cudaFuncAttributeMaxDynamicSharedMemorySize, ESMEM_BYTES);
    cudaFuncSetAttribute(node_kernel, cudaFuncAttributeMaxDynamicSharedMemorySize, NSMEM_BYTES);
    cudaFuncSetAttribute(pre_kernel,  cudaFuncAttributeMaxDynamicSharedMemorySize, P_SMEM_BYTES);

    const size_t XB = (size_t)N_NODES * 3 * sizeof(float);

    init_kernel<<<(N_NODES * HID + 255) / 256, 256>>>(z, emb, t, tw1, tb1, tw2, tb2, B);

    // ---- layer 0 ----
    pre_kernel<<<152, 512, P_SMEM_BYTES>>>(ew1 + 0 * 129 * 64, eb1 + 0 * 64);
    cudaMemcpyAsync(pxB, x, XB, cudaMemcpyDeviceToDevice, 0);
    edge_kernel<<<152, 512, ESMEM_BYTES>>>(x, pxB, ei,
        ew1 + 0 * 129 * 64 + 128 * 64, ew2 + 0 * 4096, eb2 + 0 * 64,
        cw1 + 0 * 4096, cb1 + 0 * 64, cw2 + 0 * 64, cb2 + 0, 1);
    node_kernel<<<152, 512, NSMEM_BYTES>>>(nw1 + 0 * 128 * 64, nb1 + 0 * 64,
                                           nw2 + 0 * 4096, nb2 + 0 * 64);

    // ---- layer 1 ----
    pre_kernel<<<152, 512, P_SMEM_BYTES>>>(ew1 + 1 * 129 * 64, eb1 + 1 * 64);
    cudaMemcpyAsync(pxA, pxB, XB, cudaMemcpyDeviceToDevice, 0);
    edge_kernel<<<152, 512, ESMEM_BYTES>>>(pxB, pxA, ei,
        ew1 + 1 * 129 * 64 + 128 * 64, ew2 + 1 * 4096, eb2 + 1 * 64,
        cw1 + 1 * 4096, cb1 + 1 * 64, cw2 + 1 * 64, cb2 + 1, 1);
    node_kernel<<<152, 512, NSMEM_BYTES>>>(nw1 + 1 * 128 * 64, nb1 + 1 * 64,
                                           nw2 + 1 * 4096, nb2 + 1 * 64);

    // ---- layer 2: agg/node dead, write x' straight to d_out ----
    pre_kernel<<<152, 512, P_SMEM_BYTES>>>(ew1 + 2 * 129 * 64, eb1 + 2 * 64);
    cudaMemcpyAsync(out, pxA, XB, cudaMemcpyDeviceToDevice, 0);
    edge_kernel<<<152, 512, ESMEM_BYTES>>>(pxA, out, ei,
        ew1 + 2 * 129 * 64 + 128 * 64, ew2 + 2 * 4096, eb2 + 2 * 64,
        cw1 + 2 * 4096, cb1 + 2 * 64, cw2 + 2 * 64, cb2 + 2, 0);
}

// round 6
// speedup vs baseline: 4.1775x; 1.3267x over previous
#include <cuda_runtime.h>
#include <cuda_bf16.h>
#include <cstdint>

#define N_NODES 100000
#define N_EDGES 1600000
#define HID 64
#define NGROUPS (N_EDGES / 32)       // 50000
#define NODE_GROUPS (N_NODES / 32)   // 3125

typedef unsigned long long ull;

// ---------- device scratch ----------
__device__ float g_h[N_NODES * HID];
__device__ float g_agg[N_NODES * HID];
__device__ float g_P[N_NODES * HID];
__device__ float g_Q[N_NODES * HID];
__device__ float g_xA[N_NODES * 3];
__device__ float g_xB[N_NODES * 3];

// ---------- helpers ----------
__device__ __forceinline__ ull ffma2(ull a, ull b, ull c) {
    ull d;
    asm("fma.rn.f32x2 %0, %1, %2, %3;" : "=l"(d) : "l"(a), "l"(b), "l"(c));
    return d;
}
__device__ __forceinline__ ull pack2(float x, float y) {
    ull r; asm("mov.b64 %0, {%1, %2};" : "=l"(r) : "f"(x), "f"(y)); return r;
}
__device__ __forceinline__ float2 unpack2(ull v) {
    float2 r; asm("mov.b64 {%0, %1}, %2;" : "=f"(r.x), "=f"(r.y) : "l"(v)); return r;
}
__device__ __forceinline__ float silu(float v) {
    return __fdividef(v, 1.0f + __expf(-v));
}
__device__ __forceinline__ void red_add_v2(float* addr, float a, float b) {
    asm volatile("red.global.add.v2.f32 [%0], {%1, %2};"
                 :: "l"(addr), "f"(a), "f"(b) : "memory");
}
__device__ __forceinline__ void bf16_split2(float f0, float f1, uint32_t& hi, uint32_t& lo) {
    __nv_bfloat16 h0 = __float2bfloat16(f0);
    __nv_bfloat16 h1 = __float2bfloat16(f1);
    __nv_bfloat16 l0 = __float2bfloat16(f0 - __bfloat162float(h0));
    __nv_bfloat16 l1 = __float2bfloat16(f1 - __bfloat162float(h1));
    hi = (uint32_t)__bfloat16_as_ushort(h0) | ((uint32_t)__bfloat16_as_ushort(h1) << 16);
    lo = (uint32_t)__bfloat16_as_ushort(l0) | ((uint32_t)__bfloat16_as_ushort(l1) << 16);
}
// mma.sync m16n8k16 bf16 -> f32, accumulate in place (sm_80+, valid on base compute_103)
__device__ __forceinline__ void mma16816(float c[4], const uint32_t a[4],
                                         uint32_t b0, uint32_t b1) {
    asm volatile(
        "mma.sync.aligned.m16n8k16.row.col.f32.bf16.bf16.f32 "
        "{%0,%1,%2,%3}, {%4,%5,%6,%7}, {%8,%9}, {%0,%1,%2,%3};"
        : "+f"(c[0]), "+f"(c[1]), "+f"(c[2]), "+f"(c[3])
        : "r"(a[0]), "r"(a[1]), "r"(a[2]), "r"(a[3]), "r"(b0), "r"(b1));
}

// ---------- init ----------
__global__ void init_kernel(const int* __restrict__ z, const float* __restrict__ emb,
                            const float* __restrict__ t,
                            const float* __restrict__ tw1, const float* __restrict__ tb1,
                            const float* __restrict__ tw2, const float* __restrict__ tb2,
                            int B) {
    __shared__ float s1[HID];
    __shared__ float tm[HID];
    int tidb = threadIdx.x;
    if (tidb < HID) {
        float w = tw1[tidb], bb = tb1[tidb];
        float acc = 0.f;
        for (int b = 0; b < B; b++) acc += silu(t[b] * w + bb);
        s1[tidb] = acc / (float)B;
    }
    __syncthreads();
    if (tidb < HID) {
        float o = tb2[tidb];
        for (int k = 0; k < HID; k++) o += s1[k] * tw2[k * HID + tidb];
        tm[tidb] = o;
    }
    __syncthreads();
    int i = blockIdx.x * blockDim.x + tidb;
    if (i < N_NODES * HID) {
        int node = i >> 6, j = i & 63;
        g_h[i] = emb[z[node] * HID + j] + tm[j];
        g_agg[i] = 0.f;
    }
}

// ---------- SIMT matmul helpers for pre/node kernels ----------
__device__ __forceinline__ void mm_pass16(const float* __restrict__ frow,
                                          const ulonglong2* __restrict__ W,
                                          ull acc[16]) {
    #pragma unroll 4
    for (int k = 0; k < 64; k++) {
        float f = frow[k];
        ull fd = pack2(f, f);
        #pragma unroll
        for (int q = 0; q < 8; q++) {
            ulonglong2 wv = W[k * 16 + q];
            acc[2 * q]     = ffma2(fd, wv.x, acc[2 * q]);
            acc[2 * q + 1] = ffma2(fd, wv.y, acc[2 * q + 1]);
        }
    }
}
__device__ __forceinline__ void stage_quad(float* dst, const float* __restrict__ src,
                                           int rows, int tid, int nthreads) {
    for (int i = tid; i < rows * 64; i += nthreads) {
        int k = i >> 6, c = i & 63, q = c >> 2, r = c & 3;
        int j = 2 * q + (r >> 1) + ((r & 1) << 5);
        dst[i] = src[k * 64 + j];
    }
}

// ---------- pre kernel: P = h@W1a + b1, Q = h@W1b ----------
#define P_WA   0
#define P_WB   4096
#define P_B1   8192
#define P_WARP 8256
#define P_PW   (32 * 65)
#define P_SMEMF (P_WARP + 16 * P_PW)
#define P_SMEM_BYTES (P_SMEMF * 4)

__global__ void __launch_bounds__(512, 1)
pre_kernel(const float* __restrict__ ew1, const float* __restrict__ eb1g) {
    extern __shared__ float sm[];
    const int tid = threadIdx.x;
    stage_quad(sm + P_WA, ew1, 64, tid, 512);
    stage_quad(sm + P_WB, ew1 + 64 * 64, 64, tid, 512);
    if (tid < 32) { sm[P_B1 + 2 * tid] = eb1g[tid]; sm[P_B1 + 2 * tid + 1] = eb1g[tid + 32]; }
    __syncthreads();

    const int lane = tid & 31, wrp = tid >> 5;
    float* fb = sm + P_WARP + wrp * P_PW;
    float* frow = fb + lane * 65;
    const ulonglong2* WA = (const ulonglong2*)(sm + P_WA);
    const ulonglong2* WB = (const ulonglong2*)(sm + P_WB);
    const ull* B1 = (const ull*)(sm + P_B1);

    int gw = (blockIdx.x * 512 + tid) >> 5;
    int nwrp = (gridDim.x * 512) >> 5;
    for (int g = gw; g < NODE_GROUPS; g += nwrp) {
        const int base = g * 32;
        __syncwarp();
        #pragma unroll 4
        for (int e2 = 0; e2 < 32; e2++) {
            float2 hv = *(const float2*)(g_h + (size_t)(base + e2) * 64 + 2 * lane);
            fb[e2 * 65 + 2 * lane] = hv.x;
            fb[e2 * 65 + 2 * lane + 1] = hv.y;
        }
        __syncwarp();
        float* dstP = g_P + (size_t)(base + lane) * 64;
        float* dstQ = g_Q + (size_t)(base + lane) * 64;
        #pragma unroll
        for (int mat = 0; mat < 2; mat++) {
            const ulonglong2* W = mat ? WB : WA;
            float* dst = mat ? dstQ : dstP;
            #pragma unroll
            for (int pass = 0; pass < 2; pass++) {
                ull acc[16];
                #pragma unroll
                for (int a = 0; a < 16; a++) acc[a] = mat ? 0ull : B1[16 * pass + a];
                mm_pass16(frow, W + 8 * pass, acc);
                #pragma unroll
                for (int t4 = 0; t4 < 4; t4++) {
                    float2 v0 = unpack2(acc[4 * t4 + 0]);
                    float2 v1 = unpack2(acc[4 * t4 + 1]);
                    float2 v2 = unpack2(acc[4 * t4 + 2]);
                    float2 v3 = unpack2(acc[4 * t4 + 3]);
                    *(float4*)(dst + 16 * pass + 4 * t4) = make_float4(v0.x, v1.x, v2.x, v3.x);
                    *(float4*)(dst + 16 * pass + 32 + 4 * t4) = make_float4(v0.y, v1.y, v2.y, v3.y);
                }
            }
        }
    }
}

// ---------- edge kernel (mma.sync bf16-split) ----------
// smem layout in u32 words
#define B_W2HI 0
#define B_W2LO 2304
#define B_C1HI 4608
#define B_C1LO 6912
#define SC_W1C 9216
#define SC_B2  9280
#define SC_CB1 9344
#define SC_CW2 9408
#define SC_CB2 9472
#define WARP_BASE 9480
#define WARP_W 2496          // idx/dx/r2 (192) + Ahi 1152 + Alo 1152
#define EDGE_SMEM_WORDS (WARP_BASE + 4 * WARP_W)
#define EDGE_SMEM_BYTES (EDGE_SMEM_WORDS * 4)   // 77,856 B -> 2 CTAs/SM

__global__ void __launch_bounds__(128)
edge_kernel(const float* __restrict__ x, float* __restrict__ xn,
            const int* __restrict__ ei,
            const float* __restrict__ w1c_g,
            const float* __restrict__ ew2, const float* __restrict__ eb2g,
            const float* __restrict__ cw1, const float* __restrict__ cb1g,
            const float* __restrict__ cw2g, const float* __restrict__ cb2g,
            int do_agg) {
    extern __shared__ uint32_t smw[];
    float* smf = (float*)smw;
    const int tid = threadIdx.x;

    // ---- stage B matrices: [n][kk] u32 words (bf16 pair, k even/odd), stride 36 ----
    for (int i = tid; i < 2048; i += 128) {
        int n = i >> 5, kk = i & 31;
        uint32_t hi, lo;
        bf16_split2(ew2[(2 * kk) * 64 + n], ew2[(2 * kk + 1) * 64 + n], hi, lo);
        smw[B_W2HI + n * 36 + kk] = hi;
        smw[B_W2LO + n * 36 + kk] = lo;
        bf16_split2(cw1[(2 * kk) * 64 + n], cw1[(2 * kk + 1) * 64 + n], hi, lo);
        smw[B_C1HI + n * 36 + kk] = hi;
        smw[B_C1LO + n * 36 + kk] = lo;
    }
    if (tid < 64) {
        smf[SC_W1C + tid] = w1c_g[tid];
        smf[SC_B2 + tid]  = eb2g[tid];
        smf[SC_CB1 + tid] = cb1g[tid];
        smf[SC_CW2 + tid] = cw2g[tid];
    }
    if (tid == 0) smf[SC_CB2] = cb2g[0];
    __syncthreads();

    const int lane = tid & 31;
    const int wrp = tid >> 5;
    const int g = lane >> 2;       // 0..7
    const int t = lane & 3;        // 0..3
    uint32_t* wb = smw + WARP_BASE + wrp * WARP_W;
    int* idxd = (int*)wb;
    int* idxs = idxd + 32;
    float* sdx0 = (float*)(wb + 64);
    float* sdx1 = (float*)(wb + 96);
    float* sdx2 = (float*)(wb + 128);
    float* sr2  = (float*)(wb + 160);
    uint32_t* Ah = wb + 192;
    uint32_t* Al = Ah + 1152;
    const float w1c0 = smf[SC_W1C + 2 * lane];
    const float w1c1 = smf[SC_W1C + 2 * lane + 1];
    const float cb2s = smf[SC_CB2];

    const int gwarp = (blockIdx.x * 128 + tid) >> 5;
    const int nwarps = (gridDim.x * 128) >> 5;

    for (int grp = gwarp; grp < NGROUPS; grp += nwarps) {
        const int e = grp * 32 + lane;
        const int s = ei[e];
        const int d = ei[N_EDGES + e];
        const float dx0 = __ldg(&x[d * 3 + 0]) - __ldg(&x[s * 3 + 0]);
        const float dx1 = __ldg(&x[d * 3 + 1]) - __ldg(&x[s * 3 + 1]);
        const float dx2 = __ldg(&x[d * 3 + 2]) - __ldg(&x[s * 3 + 2]);
        const float r2 = dx0 * dx0 + dx1 * dx1 + dx2 * dx2;
        __syncwarp();                  // previous group done with warp buffers
        idxd[lane] = d; idxs[lane] = s;
        sdx0[lane] = dx0; sdx1[lane] = dx1; sdx2[lane] = dx2; sr2[lane] = r2;
        __syncwarp();

        // ---- features: fb[e2][2lane..+1] = silu(P[d]+Q[s]+r2*w1c), bf16 hi/lo -> A smem ----
        #pragma unroll 4
        for (int e2 = 0; e2 < 32; e2++) {
            int nd = idxd[e2], ns = idxs[e2];
            float rr = sr2[e2];
            float2 pv = __ldg((const float2*)(g_P + (size_t)nd * 64 + 2 * lane));
            float2 qv = __ldg((const float2*)(g_Q + (size_t)ns * 64 + 2 * lane));
            float f0 = silu(fmaf(rr, w1c0, pv.x + qv.x));
            float f1 = silu(fmaf(rr, w1c1, pv.y + qv.y));
            uint32_t hi, lo;
            bf16_split2(f0, f1, hi, lo);
            Ah[e2 * 36 + lane] = hi;
            Al[e2 * 36 + lane] = lo;
        }
        __syncwarp();

        // ---- matmul1: D[32x64] = ef1 @ W2 + b2 (3-term bf16 split) ----
        float acc[16][4];      // [mt*8+nt][c0..c3]
        #pragma unroll
        for (int nt = 0; nt < 8; nt++) {
            float2 bb = *(const float2*)(smf + SC_B2 + 8 * nt + 2 * t);
            #pragma unroll
            for (int mt = 0; mt < 2; mt++) {
                acc[mt * 8 + nt][0] = bb.x; acc[mt * 8 + nt][1] = bb.y;
                acc[mt * 8 + nt][2] = bb.x; acc[mt * 8 + nt][3] = bb.y;
            }
        }
        #pragma unroll
        for (int kt = 0; kt < 4; kt++) {
            uint32_t ah[2][4], al[2][4];
            #pragma unroll
            for (int mt = 0; mt < 2; mt++) {
                int rb = (16 * mt + g) * 36 + 8 * kt + t;
                ah[mt][0] = Ah[rb];           ah[mt][1] = Ah[rb + 8 * 36];
                ah[mt][2] = Ah[rb + 4];       ah[mt][3] = Ah[rb + 8 * 36 + 4];
                al[mt][0] = Al[rb];           al[mt][1] = Al[rb + 8 * 36];
                al[mt][2] = Al[rb + 4];       al[mt][3] = Al[rb + 8 * 36 + 4];
            }
            #pragma unroll
            for (int nt = 0; nt < 8; nt++) {
                int bi = (8 * nt + g) * 36 + 8 * kt + t;
                uint32_t bh0 = smw[B_W2HI + bi], bh1 = smw[B_W2HI + bi + 4];
                uint32_t bl0 = smw[B_W2LO + bi], bl1 = smw[B_W2LO + bi + 4];
                #pragma unroll
                for (int mt = 0; mt < 2; mt++) {
                    mma16816(acc[mt * 8 + nt], ah[mt], bh0, bh1);
                    mma16816(acc[mt * 8 + nt], ah[mt], bl0, bl1);
                    mma16816(acc[mt * 8 + nt], al[mt], bh0, bh1);
                }
            }
        }

        // ---- m = silu(D); agg red.v2; convert in-register to matmul2 A fragments ----
        uint32_t mh[2][4][4], ml[2][4][4];
        int dtop[2], dbot[2];
        #pragma unroll
        for (int mt = 0; mt < 2; mt++) {
            dtop[mt] = idxd[16 * mt + g];
            dbot[mt] = idxd[16 * mt + g + 8];
        }
        #pragma unroll
        for (int mt = 0; mt < 2; mt++) {
            #pragma unroll
            for (int nt = 0; nt < 8; nt++) {
                float v0 = silu(acc[mt * 8 + nt][0]);
                float v1 = silu(acc[mt * 8 + nt][1]);
                float v2 = silu(acc[mt * 8 + nt][2]);
                float v3 = silu(acc[mt * 8 + nt][3]);
                if (do_agg) {
                    red_add_v2(&g_agg[(size_t)dtop[mt] * 64 + 8 * nt + 2 * t], v0, v1);
                    red_add_v2(&g_agg[(size_t)dbot[mt] * 64 + 8 * nt + 2 * t], v2, v3);
                }
                int kt = nt >> 1, o = (nt & 1) * 2;
                bf16_split2(v0, v1, mh[mt][kt][o], ml[mt][kt][o]);
                bf16_split2(v2, v3, mh[mt][kt][o + 1], ml[mt][kt][o + 1]);
            }
        }

        // ---- matmul2: D2 = m @ C1 + cb1 (A from registers) ----
        float acc2[16][4];
        #pragma unroll
        for (int nt = 0; nt < 8; nt++) {
            float2 bb = *(const float2*)(smf + SC_CB1 + 8 * nt + 2 * t);
            #pragma unroll
            for (int mt = 0; mt < 2; mt++) {
                acc2[mt * 8 + nt][0] = bb.x; acc2[mt * 8 + nt][1] = bb.y;
                acc2[mt * 8 + nt][2] = bb.x; acc2[mt * 8 + nt][3] = bb.y;
            }
        }
        #pragma unroll
        for (int kt = 0; kt < 4; kt++) {
            #pragma unroll
            for (int nt = 0; nt < 8; nt++) {
                int bi = (8 * nt + g) * 36 + 8 * kt + t;
                uint32_t bh0 = smw[B_C1HI + bi], bh1 = smw[B_C1HI + bi + 4];
                uint32_t bl0 = smw[B_C1LO + bi], bl1 = smw[B_C1LO + bi + 4];
                #pragma unroll
                for (int mt = 0; mt < 2; mt++) {
                    mma16816(acc2[mt * 8 + nt], mh[mt][kt], bh0, bh1);
                    mma16816(acc2[mt * 8 + nt], mh[mt][kt], bl0, bl1);
                    mma16816(acc2[mt * 8 + nt], ml[mt][kt], bh0, bh1);
                }
            }
        }

        // ---- coord epilogue: p_row = sum_j silu(D2) * cw2; quad-reduce; 3 atomics/edge ----
        float pr0 = 0.f, pr1 = 0.f, pr2 = 0.f, pr3 = 0.f;
        #pragma unroll
        for (int nt = 0; nt < 8; nt++) {
            float2 cwv = *(const float2*)(smf + SC_CW2 + 8 * nt + 2 * t);
            pr0 = fmaf(silu(acc2[nt][0]), cwv.x, pr0);
            pr0 = fmaf(silu(acc2[nt][1]), cwv.y, pr0);
            pr1 = fmaf(silu(acc2[nt][2]), cwv.x, pr1);
            pr1 = fmaf(silu(acc2[nt][3]), cwv.y, pr1);
            pr2 = fmaf(silu(acc2[8 + nt][0]), cwv.x, pr2);
            pr2 = fmaf(silu(acc2[8 + nt][1]), cwv.y, pr2);
            pr3 = fmaf(silu(acc2[8 + nt][2]), cwv.x, pr3);
            pr3 = fmaf(silu(acc2[8 + nt][3]), cwv.y, pr3);
        }
        pr0 += __shfl_xor_sync(0xffffffffu, pr0, 1);
        pr0 += __shfl_xor_sync(0xffffffffu, pr0, 2);
        pr1 += __shfl_xor_sync(0xffffffffu, pr1, 1);
        pr1 += __shfl_xor_sync(0xffffffffu, pr1, 2);
        pr2 += __shfl_xor_sync(0xffffffffu, pr2, 1);
        pr2 += __shfl_xor_sync(0xffffffffu, pr2, 2);
        pr3 += __shfl_xor_sync(0xffffffffu, pr3, 1);
        pr3 += __shfl_xor_sync(0xffffffffu, pr3, 2);
        // lane (g,t) finalizes edge e2 = g + 8*t, rows {g, g+8, 16+g, 24+g} <-> pr{0,1,2,3}
        float p = (t == 0) ? pr0 : (t == 1) ? pr1 : (t == 2) ? pr2 : pr3;
        int e2 = g + 8 * t;
        p += cb2s;
        int dd = idxd[e2];
        atomicAdd(&xn[dd * 3 + 0], sdx0[e2] * p);
        atomicAdd(&xn[dd * 3 + 1], sdx1[e2] * p);
        atomicAdd(&xn[dd * 3 + 2], sdx2[e2] * p);
    }
}

// ---------- node kernel (SIMT, round-4 design) ----------
#define ND_W1   0
#define ND_W2   8192
#define ND_B1   12288
#define ND_B2   12352
#define ND_WARP 12416
#define ND_PW   (32 * 65)
#define ND_SMEMF (ND_WARP + 16 * ND_PW)
#define NSMEM_BYTES (ND_SMEMF * 4)

__global__ void __launch_bounds__(512, 1)
node_kernel(const float* __restrict__ nw1, const float* __restrict__ nb1g,
            const float* __restrict__ nw2, const float* __restrict__ nb2g) {
    extern __shared__ float sm[];
    const int tid = threadIdx.x;
    stage_quad(sm + ND_W1, nw1, 128, tid, 512);
    stage_quad(sm + ND_W2, nw2, 64, tid, 512);
    if (tid < 32) {
        sm[ND_B1 + 2 * tid] = nb1g[tid]; sm[ND_B1 + 2 * tid + 1] = nb1g[tid + 32];
        sm[ND_B2 + 2 * tid] = nb2g[tid]; sm[ND_B2 + 2 * tid + 1] = nb2g[tid + 32];
    }
    __syncthreads();

    const int lane = tid & 31, wrp = tid >> 5;
    float* fb = sm + ND_WARP + wrp * ND_PW;
    float* frow = fb + lane * 65;
    const ulonglong2* W1v = (const ulonglong2*)(sm + ND_W1);
    const ulonglong2* W2v = (const ulonglong2*)(sm + ND_W2);
    const ull* B1 = (const ull*)(sm + ND_B1);
    const ull* B2 = (const ull*)(sm + ND_B2);

    int gw = (blockIdx.x * 512 + tid) >> 5;
    int nwrp = (gridDim.x * 512) >> 5;
    for (int g = gw; g < NODE_GROUPS; g += nwrp) {
        const int base = g * 32;
        ull acc[16];
        float mlo[16], mhi[16];
        #pragma unroll
        for (int a = 0; a < 16; a++) acc[a] = B1[a];
        __syncwarp();
        #pragma unroll 4
        for (int e2 = 0; e2 < 32; e2++) {
            float2 hv = *(const float2*)(g_h + (size_t)(base + e2) * 64 + 2 * lane);
            fb[e2 * 65 + 2 * lane] = hv.x; fb[e2 * 65 + 2 * lane + 1] = hv.y;
        }
        __syncwarp();
        mm_pass16(frow, W1v, acc);
        __syncwarp();
        #pragma unroll 4
        for (int e2 = 0; e2 < 32; e2++) {
            float2 av = *(const float2*)(g_agg + (size_t)(base + e2) * 64 + 2 * lane);
            fb[e2 * 65 + 2 * lane] = av.x; fb[e2 * 65 + 2 * lane + 1] = av.y;
        }
        __syncwarp();
        mm_pass16(frow, W1v + 64 * 16, acc);
        #pragma unroll
        for (int a = 0; a < 16; a++) {
            float2 v = unpack2(acc[a]);
            mlo[a] = silu(v.x); mhi[a] = silu(v.y);
        }
        #pragma unroll
        for (int a = 0; a < 16; a++) acc[a] = B1[16 + a];
        __syncwarp();
        #pragma unroll 4
        for (int e2 = 0; e2 < 32; e2++) {
            float2 hv = *(const float2*)(g_h + (size_t)(base + e2) * 64 + 2 * lane);
            fb[e2 * 65 + 2 * lane] = hv.x; fb[e2 * 65 + 2 * lane + 1] = hv.y;
        }
        __syncwarp();
        mm_pass16(frow, W1v + 8, acc);
        __syncwarp();
        #pragma unroll 4
        for (int e2 = 0; e2 < 32; e2++) {
            float2 av = *(const float2*)(g_agg + (size_t)(base + e2) * 64 + 2 * lane);
            fb[e2 * 65 + 2 * lane] = av.x; fb[e2 * 65 + 2 * lane + 1] = av.y;
        }
        __syncwarp();
        mm_pass16(frow, W1v + 64 * 16 + 8, acc);
        #pragma unroll
        for (int a = 0; a < 16; a++) {
            float2 v = unpack2(acc[a]);
            frow[16 + a] = silu(v.x); frow[48 + a] = silu(v.y);
        }
        #pragma unroll
        for (int a = 0; a < 16; a++) { frow[a] = mlo[a]; frow[32 + a] = mhi[a]; }

        float* hrow = g_h + (size_t)(base + lane) * 64;
        float* arow = g_agg + (size_t)(base + lane) * 64;
        #pragma unroll
        for (int pass = 0; pass < 2; pass++) {
            #pragma unroll
            for (int a = 0; a < 16; a++) acc[a] = B2[16 * pass + a];
            mm_pass16(frow, W2v + 8 * pass, acc);
            #pragma unroll
            for (int t4 = 0; t4 < 4; t4++) {
                float2 v0 = unpack2(acc[4 * t4 + 0]);
                float2 v1 = unpack2(acc[4 * t4 + 1]);
                float2 v2 = unpack2(acc[4 * t4 + 2]);
                float2 v3 = unpack2(acc[4 * t4 + 3]);
                float4 ho = *(const float4*)(hrow + 16 * pass + 4 * t4);
                ho.x += v0.x; ho.y += v1.x; ho.z += v2.x; ho.w += v3.x;
                *(float4*)(hrow + 16 * pass + 4 * t4) = ho;
                float4 hh = *(const float4*)(hrow + 16 * pass + 32 + 4 * t4);
                hh.x += v0.y; hh.y += v1.y; hh.z += v2.y; hh.w += v3.y;
                *(float4*)(hrow + 16 * pass + 32 + 4 * t4) = hh;
                *(float4*)(arow + 16 * pass + 4 * t4) = make_float4(0.f, 0.f, 0.f, 0.f);
                *(float4*)(arow + 16 * pass + 32 + 4 * t4) = make_float4(0.f, 0.f, 0.f, 0.f);
            }
        }
    }
}

// ---------- launch ----------
extern "C" void kernel_launch(void* const* d_in, const int* in_sizes, int n_in,
                              void* d_out, int out_size) {
    const float* x   = (const float*)d_in[0];
    const int*   z   = (const int*)d_in[1];
    const float* t   = (const float*)d_in[2];
    const int*   ei  = (const int*)d_in[3];
    const float* emb = (const float*)d_in[4];
    const float* tw1 = (const float*)d_in[5];
    const float* tb1 = (const float*)d_in[6];
    const float* tw2 = (const float*)d_in[7];
    const float* tb2 = (const float*)d_in[8];
    const float* ew1 = (const float*)d_in[9];
    const float* eb1 = (const float*)d_in[10];
    const float* ew2 = (const float*)d_in[11];
    const float* eb2 = (const float*)d_in[12];
    const float* cw1 = (const float*)d_in[13];
    const float* cb1 = (const float*)d_in[14];
    const float* cw2 = (const float*)d_in[15];
    const float* cb2 = (const float*)d_in[16];
    const float* nw1 = (const float*)d_in[17];
    const float* nb1 = (const float*)d_in[18];
    const float* nw2 = (const float*)d_in[19];
    const float* nb2 = (const float*)d_in[20];
    float* out = (float*)d_out;
    const int B = in_sizes[2];

    float *pxA, *pxB;
    cudaGetSymbolAddress((void**)&pxA, g_xA);
    cudaGetSymbolAddress((void**)&pxB, g_xB);

    cudaFuncSetAttribute(edge_kernel, cudaFuncAttributeMaxDynamicSharedMemorySize, EDGE_SMEM_BYTES);
    cudaFuncSetAttribute(node_kernel, cudaFuncAttributeMaxDynamicSharedMemorySize, NSMEM_BYTES);
    cudaFuncSetAttribute(pre_kernel,  cudaFuncAttributeMaxDynamicSharedMemorySize, P_SMEM_BYTES);

    const size_t XB = (size_t)N_NODES * 3 * sizeof(float);
    const int EGRID = 304;   // 2 CTAs/SM x 152 (smem-limited)

    init_kernel<<<(N_NODES * HID + 255) / 256, 256>>>(z, emb, t, tw1, tb1, tw2, tb2, B);

    // ---- layer 0 ----
    pre_kernel<<<152, 512, P_SMEM_BYTES>>>(ew1 + 0 * 129 * 64, eb1 + 0 * 64);
    cudaMemcpyAsync(pxB, x, XB, cudaMemcpyDeviceToDevice, 0);
    edge_kernel<<<EGRID, 128, EDGE_SMEM_BYTES>>>(x, pxB, ei,
        ew1 + 0 * 129 * 64 + 128 * 64, ew2 + 0 * 4096, eb2 + 0 * 64,
        cw1 + 0 * 4096, cb1 + 0 * 64, cw2 + 0 * 64, cb2 + 0, 1);
    node_kernel<<<152, 512, NSMEM_BYTES>>>(nw1 + 0 * 128 * 64, nb1 + 0 * 64,
                                           nw2 + 0 * 4096, nb2 + 0 * 64);

    // ---- layer 1 ----
    pre_kernel<<<152, 512, P_SMEM_BYTES>>>(ew1 + 1 * 129 * 64, eb1 + 1 * 64);
    cudaMemcpyAsync(pxA, pxB, XB, cudaMemcpyDeviceToDevice, 0);
    edge_kernel<<<EGRID, 128, EDGE_SMEM_BYTES>>>(pxB, pxA, ei,
        ew1 + 1 * 129 * 64 + 128 * 64, ew2 + 1 * 4096, eb2 + 1 * 64,
        cw1 + 1 * 4096, cb1 + 1 * 64, cw2 + 1 * 64, cb2 + 1, 1);
    node_kernel<<<152, 512, NSMEM_BYTES>>>(nw1 + 1 * 128 * 64, nb1 + 1 * 64,
                                           nw2 + 1 * 4096, nb2 + 1 * 64);

    // ---- layer 2: agg/node dead, write x' straight to d_out ----
    pre_kernel<<<152, 512, P_SMEM_BYTES>>>(ew1 + 2 * 129 * 64, eb1 + 2 * 64);
    cudaMemcpyAsync(out, pxA, XB, cudaMemcpyDeviceToDevice, 0);
    edge_kernel<<<EGRID, 128, EDGE_SMEM_BYTES>>>(pxA, out, ei,
        ew1 + 2 * 129 * 64 + 128 * 64, ew2 + 2 * 4096, eb2 + 2 * 64,
        cw1 + 2 * 4096, cb1 + 2 * 64, cw2 + 2 * 64, cb2 + 2, 0);
}